// round 7
// baseline (speedup 1.0000x reference)
#include <cuda_runtime.h>
#include <cuda_bf16.h>
#include <math.h>
#include <stdint.h>

#define B    128
#define L    512
#define FIN  128
#define FOUT 128
#define ALPHA 0.2f

// Scratch (device globals — no allocation allowed)
__device__ __nv_bfloat16 g_WhTh[(size_t)B * FOUT * L];  // Wh^T bf16 hi: [b][n][l]
__device__ __nv_bfloat16 g_WhTl[(size_t)B * FOUT * L];  // bf16 lo residual
__device__ __nv_bfloat16 g_WTh[FOUT * FIN];             // W^T bf16 hi: [n][k]
__device__ __nv_bfloat16 g_WTl[FOUT * FIN];             // W^T bf16 lo
__device__ float g_ei[B * L];
__device__ float g_ej[B * L];
__device__ int   g_maskKind;   // 0=int32, 1=uint8, 2=float32

// ============================ helpers ============================
__device__ __forceinline__ uint32_t smem_u32(const void* p) {
    uint32_t a;
    asm("{ .reg .u64 t; cvta.to.shared.u64 t, %1; cvt.u32.u64 %0, t; }"
        : "=r"(a) : "l"(p));
    return a;
}
__device__ __forceinline__ void ldsm_x4(uint32_t* r, uint32_t addr) {
    asm volatile("ldmatrix.sync.aligned.m8n8.x4.shared.b16 {%0,%1,%2,%3}, [%4];"
                 : "=r"(r[0]), "=r"(r[1]), "=r"(r[2]), "=r"(r[3]) : "r"(addr));
}
__device__ __forceinline__ void mma_bf16(float* c, const uint32_t* a,
                                         uint32_t b0, uint32_t b1) {
    asm volatile(
        "mma.sync.aligned.m16n8k16.row.col.f32.bf16.bf16.f32 "
        "{%0,%1,%2,%3}, {%4,%5,%6,%7}, {%8,%9}, {%0,%1,%2,%3};"
        : "+f"(c[0]), "+f"(c[1]), "+f"(c[2]), "+f"(c[3])
        : "r"(a[0]), "r"(a[1]), "r"(a[2]), "r"(a[3]), "r"(b0), "r"(b1));
}
__device__ __forceinline__ uint32_t pack_bf2(__nv_bfloat16 a, __nv_bfloat16 b) {
    return (uint32_t)__bfloat16_as_ushort(a) | ((uint32_t)__bfloat16_as_ushort(b) << 16);
}

// ---------------------------------------------------------------------------
// Kernel 0: mask-layout detect + W split/transpose ([k][n] fp32 -> [n][k] bf16
// hi/lo). One CTA; reads of W are strided but L1-resident (64KB).
// ---------------------------------------------------------------------------
__global__ void k_prep(const unsigned int* __restrict__ m,
                       const float* __restrict__ W) {
    if (threadIdx.x < 32) {
        unsigned gt1 = 0, flt = 0;
        for (int i = threadIdx.x; i < 256; i += 32) {
            unsigned w = m[i];
            if (w == 0x3F800000u) flt = 1;
            else if (w > 1u)      gt1 = 1;
        }
        unsigned bft = __ballot_sync(0xFFFFFFFFu, flt);
        unsigned bgt = __ballot_sync(0xFFFFFFFFu, gt1);
        if (threadIdx.x == 0)
            g_maskKind = bft ? 2 : (bgt ? 1 : 0);
    }
    for (int idx = threadIdx.x; idx < FIN * FOUT; idx += blockDim.x) {
        int n = idx >> 7, k = idx & 127;
        float v = W[k * FOUT + n];
        __nv_bfloat16 hi = __float2bfloat16(v);
        __nv_bfloat16 lo = __float2bfloat16(v - __bfloat162float(hi));
        g_WTh[idx] = hi;
        g_WTl[idx] = lo;
    }
}

// ---------------------------------------------------------------------------
// Kernel 1: Wh = h @ W on HMMA (split bf16, 3 chains). K streamed in 2 chunks
// of 64. Epilogue: (a) ei/ej dots from fragments (2-step shuffle reduce);
// (b) split Wh into bf16 hi/lo, stage transposed [n][m] in smem, coalesced
// store to g_WhT* [b][n][l].
// ---------------------------------------------------------------------------
#define G1_AH 0
#define G1_AL 18432
#define G1_WH 36864
#define G1_WL 55296
#define G1_AV 73728
#define G1_TOTAL 74752
#define TSTRIDE 272   // staging [n][m] bf16 row stride (128*2 + 16)

__global__ __launch_bounds__(256, 2) void k_gemm1(const float* __restrict__ h,
                                                  const float* __restrict__ a) {
    extern __shared__ char sm[];
    const uint32_t sb = smem_u32(sm);

    const int t    = threadIdx.x;
    const int wid  = t >> 5;
    const int lane = t & 31;
    const long rowBase = (long)blockIdx.x * 128;
    const int  bIdx  = (int)(rowBase >> 9);
    const int  lBase = (int)(rowBase & 511);

    if (t < 64) *(float4*)(sm + G1_AV + t * 16) = *(const float4*)(a + t * 4);

    float acc[16][4];
    #pragma unroll
    for (int n = 0; n < 16; n++)
        #pragma unroll
        for (int c = 0; c < 4; c++) acc[n][c] = 0.f;

    const int aRow  = wid * 16 + (lane & 15);
    const int aKoff = (lane >> 4) * 16;
    const uint32_t aAddrH = sb + G1_AH + aRow * 144 + aKoff;
    const uint32_t aAddrL = sb + G1_AL + aRow * 144 + aKoff;
    const int bRow  = (lane & 7) + ((lane >> 4) << 3);
    const int bKoff = ((lane >> 3) & 1) * 16;
    const uint32_t bAddrH = sb + G1_WH + bRow * 144 + bKoff;
    const uint32_t bAddrL = sb + G1_WL + bRow * 144 + bKoff;

    for (int kc = 0; kc < FIN; kc += 64) {
        __syncthreads();
        // A loader: h[m][kc..kc+63] fp32 -> split bf16 smem [m][k] (144B rows)
        #pragma unroll
        for (int i = 0; i < 8; i++) {
            const int idx = t + 256 * i;
            const int mm = idx >> 4, k4 = idx & 15;
            float4 v = *(const float4*)(h + (rowBase + mm) * FIN + kc + k4 * 4);
            __nv_bfloat16 h0 = __float2bfloat16(v.x), h1 = __float2bfloat16(v.y);
            __nv_bfloat16 h2 = __float2bfloat16(v.z), h3 = __float2bfloat16(v.w);
            uint2 hv = {pack_bf2(h0, h1), pack_bf2(h2, h3)};
            uint2 lv = {pack_bf2(__float2bfloat16(v.x - __bfloat162float(h0)),
                                 __float2bfloat16(v.y - __bfloat162float(h1))),
                        pack_bf2(__float2bfloat16(v.z - __bfloat162float(h2)),
                                 __float2bfloat16(v.w - __bfloat162float(h3)))};
            *(uint2*)(sm + G1_AH + mm * 144 + k4 * 8) = hv;
            *(uint2*)(sm + G1_AL + mm * 144 + k4 * 8) = lv;
        }
        // W loader: pre-split W^T rows, straight uint4 copies
        #pragma unroll
        for (int i = 0; i < 4; i++) {
            const int idx = t + 256 * i;
            const int n = idx >> 3, c = idx & 7;
            *(uint4*)(sm + G1_WH + n * 144 + c * 16) =
                *(const uint4*)(g_WTh + n * FIN + kc + c * 8);
            *(uint4*)(sm + G1_WL + n * 144 + c * 16) =
                *(const uint4*)(g_WTl + n * FIN + kc + c * 8);
        }
        __syncthreads();

        #pragma unroll
        for (int ks = 0; ks < 4; ks++) {
            uint32_t ah[4], al[4];
            ldsm_x4(ah, aAddrH + ks * 32);
            ldsm_x4(al, aAddrL + ks * 32);
            #pragma unroll
            for (int g = 0; g < 8; g++) {
                uint32_t bh[4], bl[4];
                ldsm_x4(bh, bAddrH + g * 16 * 144 + ks * 32);
                ldsm_x4(bl, bAddrL + g * 16 * 144 + ks * 32);
                mma_bf16(acc[g * 2],     ah, bh[0], bh[1]);
                mma_bf16(acc[g * 2 + 1], ah, bh[2], bh[3]);
                mma_bf16(acc[g * 2],     ah, bl[0], bl[1]);
                mma_bf16(acc[g * 2 + 1], ah, bl[2], bl[3]);
                mma_bf16(acc[g * 2],     al, bh[0], bh[1]);
                mma_bf16(acc[g * 2 + 1], al, bh[2], bh[3]);
            }
        }
    }

    // --- epilogue: ei/ej from fragments ---
    {
        const float* as1 = (const float*)(sm + G1_AV);
        const float* as2 = as1 + 128;
        const int k2 = (lane & 3) * 2;
        float e1a = 0.f, e2a = 0.f, e1b = 0.f, e2b = 0.f;
        #pragma unroll
        for (int nt = 0; nt < 16; nt++) {
            const int c0 = nt * 8 + k2;
            float2 a1v = *(const float2*)&as1[c0];
            float2 a2v = *(const float2*)&as2[c0];
            e1a += acc[nt][0] * a1v.x + acc[nt][1] * a1v.y;
            e2a += acc[nt][0] * a2v.x + acc[nt][1] * a2v.y;
            e1b += acc[nt][2] * a1v.x + acc[nt][3] * a1v.y;
            e2b += acc[nt][2] * a2v.x + acc[nt][3] * a2v.y;
        }
        #pragma unroll
        for (int o = 1; o <= 2; o <<= 1) {
            e1a += __shfl_xor_sync(0xFFFFFFFFu, e1a, o);
            e2a += __shfl_xor_sync(0xFFFFFFFFu, e2a, o);
            e1b += __shfl_xor_sync(0xFFFFFFFFu, e1b, o);
            e2b += __shfl_xor_sync(0xFFFFFFFFu, e2b, o);
        }
        if ((lane & 3) == 0) {
            const int r0 = wid * 16 + (lane >> 2);
            g_ei[rowBase + r0]     = e1a;
            g_ej[rowBase + r0]     = e2a;
            g_ei[rowBase + r0 + 8] = e1b;
            g_ej[rowBase + r0 + 8] = e2b;
        }
    }

    // --- epilogue: stage split WhT [n][m] in smem, coalesced store ---
    __syncthreads();
    char* TH = sm;            // 128 * 272 = 34816 (over A region)
    char* TL = sm + G1_WH;    // over W region
    {
        const int r0 = wid * 16 + (lane >> 2);
        const int k2 = (lane & 3) * 2;
        #pragma unroll
        for (int nt = 0; nt < 16; nt++) {
            const int c0 = nt * 8 + k2;
            #pragma unroll
            for (int q = 0; q < 4; q++) {
                const int cc = c0 + (q & 1);
                const int mm = r0 + (q >> 1) * 8;
                float v = acc[nt][q];
                __nv_bfloat16 hi = __float2bfloat16(v);
                __nv_bfloat16 lo = __float2bfloat16(v - __bfloat162float(hi));
                *(__nv_bfloat16*)(TH + cc * TSTRIDE + mm * 2) = hi;
                *(__nv_bfloat16*)(TL + cc * TSTRIDE + mm * 2) = lo;
            }
        }
    }
    __syncthreads();
    #pragma unroll
    for (int i = 0; i < 8; i++) {
        const int idx = t + 256 * i;
        const int n = idx >> 4, c = idx & 15;
        const size_t go = ((size_t)bIdx * FOUT + n) * L + lBase + c * 8;
        *(uint4*)(g_WhTh + go) = *(uint4*)(TH + n * TSTRIDE + c * 16);
        *(uint4*)(g_WhTl + go) = *(uint4*)(TL + n * TSTRIDE + c * 16);
    }
}

// ---------------------------------------------------------------------------
// Kernel 2: fused attention on HMMA.
//  p-phase: warp w (0-3) owns rows w*32..+31; lane l owns cols j0+2l, j0+2l+1
//   -> coalesced bias/adj loads, conflict-free STS, shuffle row sums.
//  B-copy: warps 4-7. HMMA + epilogue unchanged (validated R6).
// ---------------------------------------------------------------------------
#define SM_PH 0
#define SM_PL 18432
#define SM_BH 36864
#define SM_BL 55296
#define SM_EJ 73728                  // 512 floats
#define SM_SS 75776                  // 128 floats
#define SM_TOTAL 76288

__global__ __launch_bounds__(256, 2) void k_attn(const float* __restrict__ bias,
                                                 const void* __restrict__ adj,
                                                 float* __restrict__ out) {
    extern __shared__ char smem[];
    const uint32_t sb = smem_u32(smem);

    const int t    = threadIdx.x;
    const int wid  = t >> 5;
    const int lane = t & 31;
    const int b    = blockIdx.y;
    const int i0   = blockIdx.x * 128;

    const int kind = g_maskKind;
    const int* adjI = (const int*)adj;
    const unsigned char* adjB = (const unsigned char*)adj;
    const float* adjF = (const float*)adj;

    float* ejs  = (float*)(smem + SM_EJ);
    float* ssum = (float*)(smem + SM_SS);
    if (t < 128) *(float4*)&ejs[t * 4] = *(const float4*)&g_ej[b * L + t * 4];

    float sum_reg = 0.f;   // row sum for row wid*32 + lane (warps 0-3)

    float acc[16][4];
    #pragma unroll
    for (int n = 0; n < 16; n++)
        #pragma unroll
        for (int c = 0; c < 4; c++) acc[n][c] = 0.f;

    const int aRow  = wid * 16 + (lane & 15);
    const int aKoff = (lane >> 4) * 16;
    const uint32_t aAddrH = sb + SM_PH + aRow * 144 + aKoff;
    const uint32_t aAddrL = sb + SM_PL + aRow * 144 + aKoff;
    const int bRow  = (lane & 7) + ((lane >> 4) << 3);
    const int bKoff = ((lane >> 3) & 1) * 16;
    const uint32_t bAddrH = sb + SM_BH + bRow * 144 + bKoff;
    const uint32_t bAddrL = sb + SM_BL + bRow * 144 + bKoff;

    for (int jt = 0; jt < 8; jt++) {
        const int j0 = jt * 64;
        __syncthreads();   // previous tile's fragment reads done

        if (t < 128) {
            // ---- p-phase: warp wid owns 32 rows; lane owns 2 columns ----
            const float2 ejv = *(const float2*)&ejs[j0 + 2 * lane];
            const int mBase = wid * 32;
            const size_t rowStride = L;
            const float* bp = bias + ((size_t)b * L + i0 + mBase) * L + j0 + 2 * lane;
            const size_t adjBase = (size_t)(i0 + mBase) * L + j0 + 2 * lane;
            #pragma unroll 8
            for (int r = 0; r < 32; r++) {
                const int m = mBase + r;
                const float eim = ((const float*)(smem + SM_SS))[0] * 0.f + g_ei[b * L + i0 + m]; // see note
                float2 bv = *(const float2*)(bp + (size_t)r * rowStride);
                bool m0, m1;
                if (kind == 0) {
                    int2 w = *(const int2*)(adjI + adjBase + (size_t)r * rowStride);
                    m0 = w.x != 0; m1 = w.y != 0;
                } else if (kind == 2) {
                    float2 w = *(const float2*)(adjF + adjBase + (size_t)r * rowStride);
                    m0 = w.x != 0.f; m1 = w.y != 0.f;
                } else {
                    unsigned short w = *(const unsigned short*)(adjB + adjBase + (size_t)r * rowStride);
                    m0 = (w & 0xFFu) != 0; m1 = (w & 0xFF00u) != 0;
                }
                float x0 = eim + ejv.x;
                float x1 = eim + ejv.y;
                x0 = (x0 > 0.f ? x0 : ALPHA * x0) + bv.x;
                x1 = (x1 > 0.f ? x1 : ALPHA * x1) + bv.y;
                float p0 = m0 ? __expf(x0) : 0.f;
                float p1 = m1 ? __expf(x1) : 0.f;
                float s = p0 + p1;
                #pragma unroll
                for (int o = 16; o; o >>= 1)
                    s += __shfl_xor_sync(0xFFFFFFFFu, s, o);
                sum_reg += (lane == r) ? s : 0.f;
                __nv_bfloat16 h0 = __float2bfloat16(p0), h1 = __float2bfloat16(p1);
                uint32_t hv = pack_bf2(h0, h1);
                uint32_t lv = pack_bf2(__float2bfloat16(p0 - __bfloat162float(h0)),
                                       __float2bfloat16(p1 - __bfloat162float(h1)));
                *(uint32_t*)(smem + SM_PH + m * 144 + lane * 4) = hv;
                *(uint32_t*)(smem + SM_PL + m * 144 + lane * 4) = lv;
            }
        } else {
            // ---- B copy: smem[n][0..63] <- g_WhT*[b][n][j0..j0+63] ----
            const int u = t - 128;
            const size_t bbase = (size_t)b * FOUT * L + j0;
            #pragma unroll
            for (int r = 0; r < 8; r++) {
                const int idx = u + 128 * r;
                const int n = idx >> 3, c = idx & 7;
                const size_t so = bbase + (size_t)n * L + c * 8;
                const int d = n * 144 + c * 16;
                *(uint4*)(smem + SM_BH + d) = *(const uint4*)(g_WhTh + so);
                *(uint4*)(smem + SM_BL + d) = *(const uint4*)(g_WhTl + so);
            }
        }
        __syncthreads();

        // ---- HMMA phase ----
        #pragma unroll
        for (int ks = 0; ks < 4; ks++) {
            uint32_t ah[4], al[4];
            ldsm_x4(ah, aAddrH + ks * 32);
            ldsm_x4(al, aAddrL + ks * 32);
            #pragma unroll
            for (int g = 0; g < 8; g++) {
                uint32_t bh[4], bl[4];
                ldsm_x4(bh, bAddrH + g * 16 * 144 + ks * 32);
                ldsm_x4(bl, bAddrL + g * 16 * 144 + ks * 32);
                mma_bf16(acc[g * 2],     ah, bh[0], bh[1]);
                mma_bf16(acc[g * 2 + 1], ah, bh[2], bh[3]);
                mma_bf16(acc[g * 2],     ah, bl[0], bl[1]);
                mma_bf16(acc[g * 2 + 1], ah, bl[2], bl[3]);
                mma_bf16(acc[g * 2],     al, bh[0], bh[1]);
                mma_bf16(acc[g * 2 + 1], al, bh[2], bh[3]);
            }
        }
    }

    if (t < 128) ssum[t] = sum_reg;   // row wid*32+lane == t
    __syncthreads();

    // ---- epilogue: divide by row sum, ELU, store ----
    const int g  = lane >> 2;
    const int i2 = (lane & 3) * 2;
    const int r0 = wid * 16 + g;
    const int r1 = r0 + 8;
    const float inv0 = 1.f / ssum[r0];
    const float inv1 = 1.f / ssum[r1];
    float* o0 = out + ((size_t)b * L + i0 + r0) * FOUT;
    float* o1 = out + ((size_t)b * L + i0 + r1) * FOUT;
    #pragma unroll
    for (int nt = 0; nt < 16; nt++) {
        float v0 = acc[nt][0] * inv0, v1 = acc[nt][1] * inv0;
        float v2 = acc[nt][2] * inv1, v3 = acc[nt][3] * inv1;
        v0 = v0 > 0.f ? v0 : expm1f(v0);
        v1 = v1 > 0.f ? v1 : expm1f(v1);
        v2 = v2 > 0.f ? v2 : expm1f(v2);
        v3 = v3 > 0.f ? v3 : expm1f(v3);
        float2 w0 = {v0, v1}, w1 = {v2, v3};
        *(float2*)(o0 + nt * 8 + i2) = w0;
        *(float2*)(o1 + nt * 8 + i2) = w1;
    }
}

// ---------------------------------------------------------------------------
extern "C" void kernel_launch(void* const* d_in, const int* in_sizes, int n_in,
                              void* d_out, int out_size) {
    const float* h    = (const float*)d_in[0];
    const float* W    = (const float*)d_in[1];
    const float* a    = (const float*)d_in[2];
    const float* bias = (const float*)d_in[3];
    const void*  adj  = d_in[4];
    float* out = (float*)d_out;

    k_prep<<<1, 256>>>((const unsigned int*)adj, W);

    cudaFuncSetAttribute(k_gemm1, cudaFuncAttributeMaxDynamicSharedMemorySize, G1_TOTAL);
    k_gemm1<<<(B * L) / 128, 256, G1_TOTAL>>>(h, a);

    cudaFuncSetAttribute(k_attn, cudaFuncAttributeMaxDynamicSharedMemorySize, SM_TOTAL);
    dim3 grid(L / 128, B);
    k_attn<<<grid, 256, SM_TOTAL>>>(bias, adj, out);
}

// round 8
// speedup vs baseline: 1.8603x; 1.8603x over previous
#include <cuda_runtime.h>
#include <cuda_bf16.h>
#include <math.h>
#include <stdint.h>

#define B    128
#define L    512
#define FIN  128
#define FOUT 128
#define ALPHA 0.2f

// Scratch (device globals — no allocation allowed)
__device__ __nv_bfloat16 g_WhTh[(size_t)B * FOUT * L];  // Wh^T bf16 hi: [b][n][l]
__device__ __nv_bfloat16 g_WhTl[(size_t)B * FOUT * L];  // bf16 lo residual
__device__ __nv_bfloat16 g_WTh[FOUT * FIN];             // W^T bf16 hi: [n][k]
__device__ __nv_bfloat16 g_WTl[FOUT * FIN];             // W^T bf16 lo
__device__ float g_ei[B * L];
__device__ float g_ej[B * L];
__device__ int   g_maskKind;   // 0=int32, 1=uint8, 2=float32

// ============================ helpers ============================
__device__ __forceinline__ uint32_t smem_u32(const void* p) {
    uint32_t a;
    asm("{ .reg .u64 t; cvta.to.shared.u64 t, %1; cvt.u32.u64 %0, t; }"
        : "=r"(a) : "l"(p));
    return a;
}
__device__ __forceinline__ void ldsm_x4(uint32_t* r, uint32_t addr) {
    asm volatile("ldmatrix.sync.aligned.m8n8.x4.shared.b16 {%0,%1,%2,%3}, [%4];"
                 : "=r"(r[0]), "=r"(r[1]), "=r"(r[2]), "=r"(r[3]) : "r"(addr));
}
__device__ __forceinline__ void mma_bf16(float* c, const uint32_t* a,
                                         uint32_t b0, uint32_t b1) {
    asm volatile(
        "mma.sync.aligned.m16n8k16.row.col.f32.bf16.bf16.f32 "
        "{%0,%1,%2,%3}, {%4,%5,%6,%7}, {%8,%9}, {%0,%1,%2,%3};"
        : "+f"(c[0]), "+f"(c[1]), "+f"(c[2]), "+f"(c[3])
        : "r"(a[0]), "r"(a[1]), "r"(a[2]), "r"(a[3]), "r"(b0), "r"(b1));
}
__device__ __forceinline__ uint32_t pack_bf2(__nv_bfloat16 a, __nv_bfloat16 b) {
    return (uint32_t)__bfloat16_as_ushort(a) | ((uint32_t)__bfloat16_as_ushort(b) << 16);
}

// ---------------------------------------------------------------------------
// Kernel 0: mask-layout detect + W split/transpose ([k][n] fp32 -> [n][k] bf16)
// ---------------------------------------------------------------------------
__global__ void k_prep(const unsigned int* __restrict__ m,
                       const float* __restrict__ W) {
    if (threadIdx.x < 32) {
        unsigned gt1 = 0, flt = 0;
        for (int i = threadIdx.x; i < 256; i += 32) {
            unsigned w = m[i];
            if (w == 0x3F800000u) flt = 1;
            else if (w > 1u)      gt1 = 1;
        }
        unsigned bft = __ballot_sync(0xFFFFFFFFu, flt);
        unsigned bgt = __ballot_sync(0xFFFFFFFFu, gt1);
        if (threadIdx.x == 0)
            g_maskKind = bft ? 2 : (bgt ? 1 : 0);
    }
    for (int idx = threadIdx.x; idx < FIN * FOUT; idx += blockDim.x) {
        int n = idx >> 7, k = idx & 127;
        float v = W[k * FOUT + n];
        __nv_bfloat16 hi = __float2bfloat16(v);
        __nv_bfloat16 lo = __float2bfloat16(v - __bfloat162float(hi));
        g_WTh[idx] = hi;
        g_WTl[idx] = lo;
    }
}

// ---------------------------------------------------------------------------
// Kernel 1: Wh = h @ W on HMMA (split bf16, 3 chains). K streamed in 2 chunks
// of 64. Epilogue: ei/ej dots from fragments; split Wh staged transposed in
// smem, coalesced uint4 store to g_WhT* [b][n][l].
// ---------------------------------------------------------------------------
#define G1_AH 0
#define G1_AL 18432
#define G1_WH 36864
#define G1_WL 55296
#define G1_AV 73728
#define G1_TOTAL 74752
#define TSTRIDE 272

__global__ __launch_bounds__(256, 2) void k_gemm1(const float* __restrict__ h,
                                                  const float* __restrict__ a) {
    extern __shared__ char sm[];
    const uint32_t sb = smem_u32(sm);

    const int t    = threadIdx.x;
    const int wid  = t >> 5;
    const int lane = t & 31;
    const long rowBase = (long)blockIdx.x * 128;
    const int  bIdx  = (int)(rowBase >> 9);
    const int  lBase = (int)(rowBase & 511);

    if (t < 64) *(float4*)(sm + G1_AV + t * 16) = *(const float4*)(a + t * 4);

    float acc[16][4];
    #pragma unroll
    for (int n = 0; n < 16; n++)
        #pragma unroll
        for (int c = 0; c < 4; c++) acc[n][c] = 0.f;

    const int aRow  = wid * 16 + (lane & 15);
    const int aKoff = (lane >> 4) * 16;
    const uint32_t aAddrH = sb + G1_AH + aRow * 144 + aKoff;
    const uint32_t aAddrL = sb + G1_AL + aRow * 144 + aKoff;
    const int bRow  = (lane & 7) + ((lane >> 4) << 3);
    const int bKoff = ((lane >> 3) & 1) * 16;
    const uint32_t bAddrH = sb + G1_WH + bRow * 144 + bKoff;
    const uint32_t bAddrL = sb + G1_WL + bRow * 144 + bKoff;

    for (int kc = 0; kc < FIN; kc += 64) {
        __syncthreads();
        #pragma unroll
        for (int i = 0; i < 8; i++) {
            const int idx = t + 256 * i;
            const int mm = idx >> 4, k4 = idx & 15;
            float4 v = *(const float4*)(h + (rowBase + mm) * FIN + kc + k4 * 4);
            __nv_bfloat16 h0 = __float2bfloat16(v.x), h1 = __float2bfloat16(v.y);
            __nv_bfloat16 h2 = __float2bfloat16(v.z), h3 = __float2bfloat16(v.w);
            uint2 hv = {pack_bf2(h0, h1), pack_bf2(h2, h3)};
            uint2 lv = {pack_bf2(__float2bfloat16(v.x - __bfloat162float(h0)),
                                 __float2bfloat16(v.y - __bfloat162float(h1))),
                        pack_bf2(__float2bfloat16(v.z - __bfloat162float(h2)),
                                 __float2bfloat16(v.w - __bfloat162float(h3)))};
            *(uint2*)(sm + G1_AH + mm * 144 + k4 * 8) = hv;
            *(uint2*)(sm + G1_AL + mm * 144 + k4 * 8) = lv;
        }
        #pragma unroll
        for (int i = 0; i < 4; i++) {
            const int idx = t + 256 * i;
            const int n = idx >> 3, c = idx & 7;
            *(uint4*)(sm + G1_WH + n * 144 + c * 16) =
                *(const uint4*)(g_WTh + n * FIN + kc + c * 8);
            *(uint4*)(sm + G1_WL + n * 144 + c * 16) =
                *(const uint4*)(g_WTl + n * FIN + kc + c * 8);
        }
        __syncthreads();

        #pragma unroll
        for (int ks = 0; ks < 4; ks++) {
            uint32_t ah[4], al[4];
            ldsm_x4(ah, aAddrH + ks * 32);
            ldsm_x4(al, aAddrL + ks * 32);
            #pragma unroll
            for (int g = 0; g < 8; g++) {
                uint32_t bh[4], bl[4];
                ldsm_x4(bh, bAddrH + g * 16 * 144 + ks * 32);
                ldsm_x4(bl, bAddrL + g * 16 * 144 + ks * 32);
                mma_bf16(acc[g * 2],     ah, bh[0], bh[1]);
                mma_bf16(acc[g * 2 + 1], ah, bh[2], bh[3]);
                mma_bf16(acc[g * 2],     ah, bl[0], bl[1]);
                mma_bf16(acc[g * 2 + 1], ah, bl[2], bl[3]);
                mma_bf16(acc[g * 2],     al, bh[0], bh[1]);
                mma_bf16(acc[g * 2 + 1], al, bh[2], bh[3]);
            }
        }
    }

    // --- epilogue: ei/ej from fragments ---
    {
        const float* as1 = (const float*)(sm + G1_AV);
        const float* as2 = as1 + 128;
        const int k2 = (lane & 3) * 2;
        float e1a = 0.f, e2a = 0.f, e1b = 0.f, e2b = 0.f;
        #pragma unroll
        for (int nt = 0; nt < 16; nt++) {
            const int c0 = nt * 8 + k2;
            float2 a1v = *(const float2*)&as1[c0];
            float2 a2v = *(const float2*)&as2[c0];
            e1a += acc[nt][0] * a1v.x + acc[nt][1] * a1v.y;
            e2a += acc[nt][0] * a2v.x + acc[nt][1] * a2v.y;
            e1b += acc[nt][2] * a1v.x + acc[nt][3] * a1v.y;
            e2b += acc[nt][2] * a2v.x + acc[nt][3] * a2v.y;
        }
        #pragma unroll
        for (int o = 1; o <= 2; o <<= 1) {
            e1a += __shfl_xor_sync(0xFFFFFFFFu, e1a, o);
            e2a += __shfl_xor_sync(0xFFFFFFFFu, e2a, o);
            e1b += __shfl_xor_sync(0xFFFFFFFFu, e1b, o);
            e2b += __shfl_xor_sync(0xFFFFFFFFu, e2b, o);
        }
        if ((lane & 3) == 0) {
            const int r0 = wid * 16 + (lane >> 2);
            g_ei[rowBase + r0]     = e1a;
            g_ej[rowBase + r0]     = e2a;
            g_ei[rowBase + r0 + 8] = e1b;
            g_ej[rowBase + r0 + 8] = e2b;
        }
    }

    // --- epilogue: stage split WhT [n][m] in smem, coalesced store ---
    __syncthreads();
    char* TH = sm;
    char* TL = sm + G1_WH;
    {
        const int r0 = wid * 16 + (lane >> 2);
        const int k2 = (lane & 3) * 2;
        #pragma unroll
        for (int nt = 0; nt < 16; nt++) {
            const int c0 = nt * 8 + k2;
            #pragma unroll
            for (int q = 0; q < 4; q++) {
                const int cc = c0 + (q & 1);
                const int mm = r0 + (q >> 1) * 8;
                float v = acc[nt][q];
                __nv_bfloat16 hi = __float2bfloat16(v);
                __nv_bfloat16 lo = __float2bfloat16(v - __bfloat162float(hi));
                *(__nv_bfloat16*)(TH + cc * TSTRIDE + mm * 2) = hi;
                *(__nv_bfloat16*)(TL + cc * TSTRIDE + mm * 2) = lo;
            }
        }
    }
    __syncthreads();
    #pragma unroll
    for (int i = 0; i < 8; i++) {
        const int idx = t + 256 * i;
        const int n = idx >> 4, c = idx & 15;
        const size_t go = ((size_t)bIdx * FOUT + n) * L + lBase + c * 8;
        *(uint4*)(g_WhTh + go) = *(uint4*)(TH + n * TSTRIDE + c * 16);
        *(uint4*)(g_WhTl + go) = *(uint4*)(TL + n * TSTRIDE + c * 16);
    }
}

// ---------------------------------------------------------------------------
// Kernel 2: fused attention on HMMA — exact R6 version (validated, 254.5us).
//  Phase A per tile: warps 0-3 compute p rows exactly in fp32 (+row sums),
//    store bf16 hi/lo to smem; warps 4-7 copy pre-split Wh^T tile to smem.
//  Phase B: all 8 warps HMMA, 3 chains: ph*wh + ph*wl + pl*wh.
// ---------------------------------------------------------------------------
#define SM_PH 0
#define SM_PL 18432
#define SM_BH 36864
#define SM_BL 55296
#define SM_EJ 73728
#define SM_SS 75776
#define SM_TOTAL 76288

__global__ __launch_bounds__(256, 2) void k_attn(const float* __restrict__ bias,
                                                 const void* __restrict__ adj,
                                                 float* __restrict__ out) {
    extern __shared__ char smem[];
    const uint32_t sb = smem_u32(smem);

    const int t    = threadIdx.x;
    const int wid  = t >> 5;
    const int lane = t & 31;
    const int b    = blockIdx.y;
    const int i0   = blockIdx.x * 128;

    const int kind = g_maskKind;
    const int* adjI = (const int*)adj;
    const unsigned char* adjB = (const unsigned char*)adj;
    const float* adjF = (const float*)adj;

    float* ejs  = (float*)(smem + SM_EJ);
    float* ssum = (float*)(smem + SM_SS);
    if (t < 128) *(float4*)&ejs[t * 4] = *(const float4*)&g_ej[b * L + t * 4];

    float ei_m = 0.f, sum_m = 0.f;
    if (t < 128) ei_m = g_ei[b * L + i0 + t];

    float acc[16][4];
    #pragma unroll
    for (int n = 0; n < 16; n++)
        #pragma unroll
        for (int c = 0; c < 4; c++) acc[n][c] = 0.f;

    const int aRow  = wid * 16 + (lane & 15);
    const int aKoff = (lane >> 4) * 16;
    const uint32_t aAddrH = sb + SM_PH + aRow * 144 + aKoff;
    const uint32_t aAddrL = sb + SM_PL + aRow * 144 + aKoff;
    const int bRow  = (lane & 7) + ((lane >> 4) << 3);
    const int bKoff = ((lane >> 3) & 1) * 16;
    const uint32_t bAddrH = sb + SM_BH + bRow * 144 + bKoff;
    const uint32_t bAddrL = sb + SM_BL + bRow * 144 + bKoff;

    for (int jt = 0; jt < 8; jt++) {
        const int j0 = jt * 64;
        __syncthreads();

        if (t < 128) {
            const int m = t;
            const float* bRowP = bias + ((size_t)b * L + i0 + m) * L + j0;
            const size_t adjRow = (size_t)(i0 + m) * L + j0;
            char* ph = smem + SM_PH + m * 144;
            char* pl = smem + SM_PL + m * 144;
            #pragma unroll
            for (int c4 = 0; c4 < 16; c4++) {
                const int j = c4 * 4;
                float4 bv = *(const float4*)(bRowP + j);
                bool m0, m1, m2, m3;
                if (kind == 0) {
                    int4 w = *(const int4*)(adjI + adjRow + j);
                    m0 = w.x != 0; m1 = w.y != 0; m2 = w.z != 0; m3 = w.w != 0;
                } else if (kind == 2) {
                    float4 w = *(const float4*)(adjF + adjRow + j);
                    m0 = w.x != 0.f; m1 = w.y != 0.f; m2 = w.z != 0.f; m3 = w.w != 0.f;
                } else {
                    uint32_t w = *(const uint32_t*)(adjB + adjRow + j);
                    m0 = (w & 0xFFu) != 0; m1 = (w & 0xFF00u) != 0;
                    m2 = (w & 0xFF0000u) != 0; m3 = (w & 0xFF000000u) != 0;
                }
                float x0 = ei_m + ejs[j0 + j];
                float x1 = ei_m + ejs[j0 + j + 1];
                float x2 = ei_m + ejs[j0 + j + 2];
                float x3 = ei_m + ejs[j0 + j + 3];
                x0 = (x0 > 0.f ? x0 : ALPHA * x0) + bv.x;
                x1 = (x1 > 0.f ? x1 : ALPHA * x1) + bv.y;
                x2 = (x2 > 0.f ? x2 : ALPHA * x2) + bv.z;
                x3 = (x3 > 0.f ? x3 : ALPHA * x3) + bv.w;
                float p0 = m0 ? __expf(x0) : 0.f;
                float p1 = m1 ? __expf(x1) : 0.f;
                float p2 = m2 ? __expf(x2) : 0.f;
                float p3 = m3 ? __expf(x3) : 0.f;
                sum_m += (p0 + p1) + (p2 + p3);
                __nv_bfloat16 h0 = __float2bfloat16(p0), h1 = __float2bfloat16(p1);
                __nv_bfloat16 h2 = __float2bfloat16(p2), h3 = __float2bfloat16(p3);
                uint2 hv = {pack_bf2(h0, h1), pack_bf2(h2, h3)};
                uint2 lv = {pack_bf2(__float2bfloat16(p0 - __bfloat162float(h0)),
                                     __float2bfloat16(p1 - __bfloat162float(h1))),
                            pack_bf2(__float2bfloat16(p2 - __bfloat162float(h2)),
                                     __float2bfloat16(p3 - __bfloat162float(h3)))};
                *(uint2*)(ph + j * 2) = hv;
                *(uint2*)(pl + j * 2) = lv;
            }
        } else {
            const int u = t - 128;
            const size_t bbase = (size_t)b * FOUT * L + j0;
            #pragma unroll
            for (int r = 0; r < 8; r++) {
                const int idx = u + 128 * r;
                const int n = idx >> 3, c = idx & 7;
                const size_t so = bbase + (size_t)n * L + c * 8;
                const int d = n * 144 + c * 16;
                *(uint4*)(smem + SM_BH + d) = *(const uint4*)(g_WhTh + so);
                *(uint4*)(smem + SM_BL + d) = *(const uint4*)(g_WhTl + so);
            }
        }
        __syncthreads();

        #pragma unroll
        for (int ks = 0; ks < 4; ks++) {
            uint32_t ah[4], al[4];
            ldsm_x4(ah, aAddrH + ks * 32);
            ldsm_x4(al, aAddrL + ks * 32);
            #pragma unroll
            for (int nt2 = 0; nt2 < 8; nt2++) {
                uint32_t bh[4], bl[4];
                ldsm_x4(bh, bAddrH + nt2 * 16 * 144 + ks * 32);
                ldsm_x4(bl, bAddrL + nt2 * 16 * 144 + ks * 32);
                mma_bf16(acc[nt2 * 2],     ah, bh[0], bh[1]);
                mma_bf16(acc[nt2 * 2 + 1], ah, bh[2], bh[3]);
                mma_bf16(acc[nt2 * 2],     ah, bl[0], bl[1]);
                mma_bf16(acc[nt2 * 2 + 1], ah, bl[2], bl[3]);
                mma_bf16(acc[nt2 * 2],     al, bh[0], bh[1]);
                mma_bf16(acc[nt2 * 2 + 1], al, bh[2], bh[3]);
            }
        }
    }

    if (t < 128) ssum[t] = sum_m;
    __syncthreads();

    const int g  = lane >> 2;
    const int i2 = (lane & 3) * 2;
    const int r0 = wid * 16 + g;
    const int r1 = r0 + 8;
    const float inv0 = 1.f / ssum[r0];
    const float inv1 = 1.f / ssum[r1];
    float* o0 = out + ((size_t)b * L + i0 + r0) * FOUT;
    float* o1 = out + ((size_t)b * L + i0 + r1) * FOUT;
    #pragma unroll
    for (int nt = 0; nt < 16; nt++) {
        float v0 = acc[nt][0] * inv0, v1 = acc[nt][1] * inv0;
        float v2 = acc[nt][2] * inv1, v3 = acc[nt][3] * inv1;
        v0 = v0 > 0.f ? v0 : expm1f(v0);
        v1 = v1 > 0.f ? v1 : expm1f(v1);
        v2 = v2 > 0.f ? v2 : expm1f(v2);
        v3 = v3 > 0.f ? v3 : expm1f(v3);
        float2 w0 = {v0, v1}, w1 = {v2, v3};
        *(float2*)(o0 + nt * 8 + i2) = w0;
        *(float2*)(o1 + nt * 8 + i2) = w1;
    }
}

// ---------------------------------------------------------------------------
extern "C" void kernel_launch(void* const* d_in, const int* in_sizes, int n_in,
                              void* d_out, int out_size) {
    const float* h    = (const float*)d_in[0];
    const float* W    = (const float*)d_in[1];
    const float* a    = (const float*)d_in[2];
    const float* bias = (const float*)d_in[3];
    const void*  adj  = d_in[4];
    float* out = (float*)d_out;

    k_prep<<<1, 256>>>((const unsigned int*)adj, W);

    cudaFuncSetAttribute(k_gemm1, cudaFuncAttributeMaxDynamicSharedMemorySize, G1_TOTAL);
    k_gemm1<<<(B * L) / 128, 256, G1_TOTAL>>>(h, a);

    cudaFuncSetAttribute(k_attn, cudaFuncAttributeMaxDynamicSharedMemorySize, SM_TOTAL);
    dim3 grid(L / 128, B);
    k_attn<<<grid, 256, SM_TOTAL>>>(bias, adj, out);
}

// round 9
// speedup vs baseline: 2.2981x; 1.2353x over previous
#include <cuda_runtime.h>
#include <cuda_bf16.h>
#include <cuda_fp16.h>
#include <math.h>
#include <stdint.h>

#define B    128
#define L    512
#define FIN  128
#define FOUT 128
#define ALPHA 0.2f

// Scratch (device globals — no allocation allowed)
__device__ __half g_WhT[(size_t)B * FOUT * L];          // Wh^T fp16: [b][n][l]
__device__ __nv_bfloat16 g_WTh[FOUT * FIN];             // W^T bf16 hi: [n][k]
__device__ __nv_bfloat16 g_WTl[FOUT * FIN];             // W^T bf16 lo
__device__ float g_ei[B * L];
__device__ float g_ej[B * L];
__device__ int   g_maskKind;   // 0=int32, 1=uint8, 2=float32

// ============================ helpers ============================
__device__ __forceinline__ uint32_t smem_u32(const void* p) {
    uint32_t a;
    asm("{ .reg .u64 t; cvta.to.shared.u64 t, %1; cvt.u32.u64 %0, t; }"
        : "=r"(a) : "l"(p));
    return a;
}
__device__ __forceinline__ void ldsm_x4(uint32_t* r, uint32_t addr) {
    asm volatile("ldmatrix.sync.aligned.m8n8.x4.shared.b16 {%0,%1,%2,%3}, [%4];"
                 : "=r"(r[0]), "=r"(r[1]), "=r"(r[2]), "=r"(r[3]) : "r"(addr));
}
__device__ __forceinline__ void mma_bf16(float* c, const uint32_t* a,
                                         uint32_t b0, uint32_t b1) {
    asm volatile(
        "mma.sync.aligned.m16n8k16.row.col.f32.bf16.bf16.f32 "
        "{%0,%1,%2,%3}, {%4,%5,%6,%7}, {%8,%9}, {%0,%1,%2,%3};"
        : "+f"(c[0]), "+f"(c[1]), "+f"(c[2]), "+f"(c[3])
        : "r"(a[0]), "r"(a[1]), "r"(a[2]), "r"(a[3]), "r"(b0), "r"(b1));
}
__device__ __forceinline__ void mma_f16(float* c, const uint32_t* a,
                                        uint32_t b0, uint32_t b1) {
    asm volatile(
        "mma.sync.aligned.m16n8k16.row.col.f32.f16.f16.f32 "
        "{%0,%1,%2,%3}, {%4,%5,%6,%7}, {%8,%9}, {%0,%1,%2,%3};"
        : "+f"(c[0]), "+f"(c[1]), "+f"(c[2]), "+f"(c[3])
        : "r"(a[0]), "r"(a[1]), "r"(a[2]), "r"(a[3]), "r"(b0), "r"(b1));
}
__device__ __forceinline__ uint32_t pack_bf2(__nv_bfloat16 a, __nv_bfloat16 b) {
    return (uint32_t)__bfloat16_as_ushort(a) | ((uint32_t)__bfloat16_as_ushort(b) << 16);
}
__device__ __forceinline__ uint32_t pack_h2(float a, float b) {
    __half2 h = __floats2half2_rn(a, b);
    return *(uint32_t*)&h;
}

// ---------------------------------------------------------------------------
// Kernel 0: mask-layout detect (block 0) + W split/transpose (all 64 blocks)
// ---------------------------------------------------------------------------
__global__ void k_prep(const unsigned int* __restrict__ m,
                       const float* __restrict__ W) {
    if (blockIdx.x == 0 && threadIdx.x < 32) {
        unsigned gt1 = 0, flt = 0;
        for (int i = threadIdx.x; i < 256; i += 32) {
            unsigned w = m[i];
            if (w == 0x3F800000u) flt = 1;
            else if (w > 1u)      gt1 = 1;
        }
        unsigned bft = __ballot_sync(0xFFFFFFFFu, flt);
        unsigned bgt = __ballot_sync(0xFFFFFFFFu, gt1);
        if (threadIdx.x == 0)
            g_maskKind = bft ? 2 : (bgt ? 1 : 0);
    }
    for (int idx = blockIdx.x * blockDim.x + threadIdx.x; idx < FIN * FOUT;
         idx += gridDim.x * blockDim.x) {
        int n = idx >> 7, k = idx & 127;
        float v = W[k * FOUT + n];
        __nv_bfloat16 hi = __float2bfloat16(v);
        __nv_bfloat16 lo = __float2bfloat16(v - __bfloat162float(hi));
        g_WTh[idx] = hi;
        g_WTl[idx] = lo;
    }
}

// ---------------------------------------------------------------------------
// Kernel 1: Wh = h @ W on HMMA (split bf16, 3 chains — Wh/ei/ej need ~1e-5).
// Epilogue: ei/ej dots from fragments; Wh -> fp16, staged transposed in smem,
// coalesced uint4 store to g_WhT [b][n][l].
// ---------------------------------------------------------------------------
#define G1_AH 0
#define G1_AL 18432
#define G1_WH 36864
#define G1_WL 55296
#define G1_AV 73728
#define G1_TOTAL 74752
#define TSTRIDE 272

__global__ __launch_bounds__(256, 2) void k_gemm1(const float* __restrict__ h,
                                                  const float* __restrict__ a) {
    extern __shared__ char sm[];
    const uint32_t sb = smem_u32(sm);

    const int t    = threadIdx.x;
    const int wid  = t >> 5;
    const int lane = t & 31;
    const long rowBase = (long)blockIdx.x * 128;
    const int  bIdx  = (int)(rowBase >> 9);
    const int  lBase = (int)(rowBase & 511);

    if (t < 64) *(float4*)(sm + G1_AV + t * 16) = *(const float4*)(a + t * 4);

    float acc[16][4];
    #pragma unroll
    for (int n = 0; n < 16; n++)
        #pragma unroll
        for (int c = 0; c < 4; c++) acc[n][c] = 0.f;

    const int aRow  = wid * 16 + (lane & 15);
    const int aKoff = (lane >> 4) * 16;
    const uint32_t aAddrH = sb + G1_AH + aRow * 144 + aKoff;
    const uint32_t aAddrL = sb + G1_AL + aRow * 144 + aKoff;
    const int bRow  = (lane & 7) + ((lane >> 4) << 3);
    const int bKoff = ((lane >> 3) & 1) * 16;
    const uint32_t bAddrH = sb + G1_WH + bRow * 144 + bKoff;
    const uint32_t bAddrL = sb + G1_WL + bRow * 144 + bKoff;

    for (int kc = 0; kc < FIN; kc += 64) {
        __syncthreads();
        #pragma unroll
        for (int i = 0; i < 8; i++) {
            const int idx = t + 256 * i;
            const int mm = idx >> 4, k4 = idx & 15;
            float4 v = *(const float4*)(h + (rowBase + mm) * FIN + kc + k4 * 4);
            __nv_bfloat16 h0 = __float2bfloat16(v.x), h1 = __float2bfloat16(v.y);
            __nv_bfloat16 h2 = __float2bfloat16(v.z), h3 = __float2bfloat16(v.w);
            uint2 hv = {pack_bf2(h0, h1), pack_bf2(h2, h3)};
            uint2 lv = {pack_bf2(__float2bfloat16(v.x - __bfloat162float(h0)),
                                 __float2bfloat16(v.y - __bfloat162float(h1))),
                        pack_bf2(__float2bfloat16(v.z - __bfloat162float(h2)),
                                 __float2bfloat16(v.w - __bfloat162float(h3)))};
            *(uint2*)(sm + G1_AH + mm * 144 + k4 * 8) = hv;
            *(uint2*)(sm + G1_AL + mm * 144 + k4 * 8) = lv;
        }
        #pragma unroll
        for (int i = 0; i < 4; i++) {
            const int idx = t + 256 * i;
            const int n = idx >> 3, c = idx & 7;
            *(uint4*)(sm + G1_WH + n * 144 + c * 16) =
                *(const uint4*)(g_WTh + n * FIN + kc + c * 8);
            *(uint4*)(sm + G1_WL + n * 144 + c * 16) =
                *(const uint4*)(g_WTl + n * FIN + kc + c * 8);
        }
        __syncthreads();

        #pragma unroll
        for (int ks = 0; ks < 4; ks++) {
            uint32_t ah[4], al[4];
            ldsm_x4(ah, aAddrH + ks * 32);
            ldsm_x4(al, aAddrL + ks * 32);
            #pragma unroll
            for (int g = 0; g < 8; g++) {
                uint32_t bh[4], bl[4];
                ldsm_x4(bh, bAddrH + g * 16 * 144 + ks * 32);
                ldsm_x4(bl, bAddrL + g * 16 * 144 + ks * 32);
                mma_bf16(acc[g * 2],     ah, bh[0], bh[1]);
                mma_bf16(acc[g * 2 + 1], ah, bh[2], bh[3]);
                mma_bf16(acc[g * 2],     ah, bl[0], bl[1]);
                mma_bf16(acc[g * 2 + 1], ah, bl[2], bl[3]);
                mma_bf16(acc[g * 2],     al, bh[0], bh[1]);
                mma_bf16(acc[g * 2 + 1], al, bh[2], bh[3]);
            }
        }
    }

    // --- epilogue: ei/ej from fragments ---
    {
        const float* as1 = (const float*)(sm + G1_AV);
        const float* as2 = as1 + 128;
        const int k2 = (lane & 3) * 2;
        float e1a = 0.f, e2a = 0.f, e1b = 0.f, e2b = 0.f;
        #pragma unroll
        for (int nt = 0; nt < 16; nt++) {
            const int c0 = nt * 8 + k2;
            float2 a1v = *(const float2*)&as1[c0];
            float2 a2v = *(const float2*)&as2[c0];
            e1a += acc[nt][0] * a1v.x + acc[nt][1] * a1v.y;
            e2a += acc[nt][0] * a2v.x + acc[nt][1] * a2v.y;
            e1b += acc[nt][2] * a1v.x + acc[nt][3] * a1v.y;
            e2b += acc[nt][2] * a2v.x + acc[nt][3] * a2v.y;
        }
        #pragma unroll
        for (int o = 1; o <= 2; o <<= 1) {
            e1a += __shfl_xor_sync(0xFFFFFFFFu, e1a, o);
            e2a += __shfl_xor_sync(0xFFFFFFFFu, e2a, o);
            e1b += __shfl_xor_sync(0xFFFFFFFFu, e1b, o);
            e2b += __shfl_xor_sync(0xFFFFFFFFu, e2b, o);
        }
        if ((lane & 3) == 0) {
            const int r0 = wid * 16 + (lane >> 2);
            g_ei[rowBase + r0]     = e1a;
            g_ej[rowBase + r0]     = e2a;
            g_ei[rowBase + r0 + 8] = e1b;
            g_ej[rowBase + r0 + 8] = e2b;
        }
    }

    // --- epilogue: stage fp16 WhT [n][m] in smem, coalesced store ---
    __syncthreads();
    char* TH = sm;   // 128 * 272 = 34816 bytes
    {
        const int r0 = wid * 16 + (lane >> 2);
        const int k2 = (lane & 3) * 2;
        #pragma unroll
        for (int nt = 0; nt < 16; nt++) {
            const int c0 = nt * 8 + k2;
            #pragma unroll
            for (int q = 0; q < 4; q++) {
                const int cc = c0 + (q & 1);
                const int mm = r0 + (q >> 1) * 8;
                *(__half*)(TH + cc * TSTRIDE + mm * 2) = __float2half_rn(acc[nt][q]);
            }
        }
    }
    __syncthreads();
    #pragma unroll
    for (int i = 0; i < 8; i++) {
        const int idx = t + 256 * i;
        const int n = idx >> 4, c = idx & 15;
        const size_t go = ((size_t)bIdx * FOUT + n) * L + lBase + c * 8;
        *(uint4*)(g_WhT + go) = *(uint4*)(TH + n * TSTRIDE + c * 16);
    }
}

// ---------------------------------------------------------------------------
// Kernel 2: fused attention, single-chain fp16 HMMA (FlashAttention-style P@V).
//  Phase A per tile: warps 0-3 compute p rows exactly in fp32 (+row sums),
//    store fp16 to smem; warps 4-7 copy fp16 Wh^T tile.
//  Phase B: all 8 warps, 1 MMA chain (p16 @ Wh16).
// ---------------------------------------------------------------------------
#define SM_PH 0
#define SM_BH 18432
#define SM_EJ 36864
#define SM_SS 38912
#define SM_TOTAL 39424

__global__ __launch_bounds__(256, 2) void k_attn(const float* __restrict__ bias,
                                                 const void* __restrict__ adj,
                                                 float* __restrict__ out) {
    extern __shared__ char smem[];
    const uint32_t sb = smem_u32(smem);

    const int t    = threadIdx.x;
    const int wid  = t >> 5;
    const int lane = t & 31;
    const int b    = blockIdx.y;
    const int i0   = blockIdx.x * 128;

    const int kind = g_maskKind;
    const int* adjI = (const int*)adj;
    const unsigned char* adjB = (const unsigned char*)adj;
    const float* adjF = (const float*)adj;

    float* ejs  = (float*)(smem + SM_EJ);
    float* ssum = (float*)(smem + SM_SS);
    if (t < 128) *(float4*)&ejs[t * 4] = *(const float4*)&g_ej[b * L + t * 4];

    float ei_m = 0.f, sum_m = 0.f;
    if (t < 128) ei_m = g_ei[b * L + i0 + t];

    float acc[16][4];
    #pragma unroll
    for (int n = 0; n < 16; n++)
        #pragma unroll
        for (int c = 0; c < 4; c++) acc[n][c] = 0.f;

    const int aRow  = wid * 16 + (lane & 15);
    const int aKoff = (lane >> 4) * 16;
    const uint32_t aAddr = sb + SM_PH + aRow * 144 + aKoff;
    const int bRow  = (lane & 7) + ((lane >> 4) << 3);
    const int bKoff = ((lane >> 3) & 1) * 16;
    const uint32_t bAddr = sb + SM_BH + bRow * 144 + bKoff;

    for (int jt = 0; jt < 8; jt++) {
        const int j0 = jt * 64;
        __syncthreads();

        if (t < 128) {
            const int m = t;
            const float* bRowP = bias + ((size_t)b * L + i0 + m) * L + j0;
            const size_t adjRow = (size_t)(i0 + m) * L + j0;
            char* ph = smem + SM_PH + m * 144;
            #pragma unroll
            for (int c4 = 0; c4 < 16; c4++) {
                const int j = c4 * 4;
                float4 bv = *(const float4*)(bRowP + j);
                bool m0, m1, m2, m3;
                if (kind == 0) {
                    int4 w = *(const int4*)(adjI + adjRow + j);
                    m0 = w.x != 0; m1 = w.y != 0; m2 = w.z != 0; m3 = w.w != 0;
                } else if (kind == 2) {
                    float4 w = *(const float4*)(adjF + adjRow + j);
                    m0 = w.x != 0.f; m1 = w.y != 0.f; m2 = w.z != 0.f; m3 = w.w != 0.f;
                } else {
                    uint32_t w = *(const uint32_t*)(adjB + adjRow + j);
                    m0 = (w & 0xFFu) != 0; m1 = (w & 0xFF00u) != 0;
                    m2 = (w & 0xFF0000u) != 0; m3 = (w & 0xFF000000u) != 0;
                }
                float x0 = ei_m + ejs[j0 + j];
                float x1 = ei_m + ejs[j0 + j + 1];
                float x2 = ei_m + ejs[j0 + j + 2];
                float x3 = ei_m + ejs[j0 + j + 3];
                x0 = (x0 > 0.f ? x0 : ALPHA * x0) + bv.x;
                x1 = (x1 > 0.f ? x1 : ALPHA * x1) + bv.y;
                x2 = (x2 > 0.f ? x2 : ALPHA * x2) + bv.z;
                x3 = (x3 > 0.f ? x3 : ALPHA * x3) + bv.w;
                float p0 = m0 ? __expf(x0) : 0.f;
                float p1 = m1 ? __expf(x1) : 0.f;
                float p2 = m2 ? __expf(x2) : 0.f;
                float p3 = m3 ? __expf(x3) : 0.f;
                sum_m += (p0 + p1) + (p2 + p3);
                uint2 hv = {pack_h2(p0, p1), pack_h2(p2, p3)};
                *(uint2*)(ph + j * 2) = hv;
            }
        } else {
            const int u = t - 128;
            const size_t bbase = (size_t)b * FOUT * L + j0;
            #pragma unroll
            for (int r = 0; r < 8; r++) {
                const int idx = u + 128 * r;
                const int n = idx >> 3, c = idx & 7;
                const size_t so = bbase + (size_t)n * L + c * 8;
                const int d = n * 144 + c * 16;
                *(uint4*)(smem + SM_BH + d) = *(const uint4*)(g_WhT + so);
            }
        }
        __syncthreads();

        #pragma unroll
        for (int ks = 0; ks < 4; ks++) {
            uint32_t ap[4];
            ldsm_x4(ap, aAddr + ks * 32);
            #pragma unroll
            for (int g = 0; g < 8; g++) {
                uint32_t bw[4];
                ldsm_x4(bw, bAddr + g * 16 * 144 + ks * 32);
                mma_f16(acc[g * 2],     ap, bw[0], bw[1]);
                mma_f16(acc[g * 2 + 1], ap, bw[2], bw[3]);
            }
        }
    }

    if (t < 128) ssum[t] = sum_m;
    __syncthreads();

    const int g  = lane >> 2;
    const int i2 = (lane & 3) * 2;
    const int r0 = wid * 16 + g;
    const int r1 = r0 + 8;
    const float inv0 = 1.f / ssum[r0];
    const float inv1 = 1.f / ssum[r1];
    float* o0 = out + ((size_t)b * L + i0 + r0) * FOUT;
    float* o1 = out + ((size_t)b * L + i0 + r1) * FOUT;
    #pragma unroll
    for (int nt = 0; nt < 16; nt++) {
        float v0 = acc[nt][0] * inv0, v1 = acc[nt][1] * inv0;
        float v2 = acc[nt][2] * inv1, v3 = acc[nt][3] * inv1;
        v0 = v0 > 0.f ? v0 : expm1f(v0);
        v1 = v1 > 0.f ? v1 : expm1f(v1);
        v2 = v2 > 0.f ? v2 : expm1f(v2);
        v3 = v3 > 0.f ? v3 : expm1f(v3);
        float2 w0 = {v0, v1}, w1 = {v2, v3};
        *(float2*)(o0 + nt * 8 + i2) = w0;
        *(float2*)(o1 + nt * 8 + i2) = w1;
    }
}

// ---------------------------------------------------------------------------
extern "C" void kernel_launch(void* const* d_in, const int* in_sizes, int n_in,
                              void* d_out, int out_size) {
    const float* h    = (const float*)d_in[0];
    const float* W    = (const float*)d_in[1];
    const float* a    = (const float*)d_in[2];
    const float* bias = (const float*)d_in[3];
    const void*  adj  = d_in[4];
    float* out = (float*)d_out;

    k_prep<<<64, 256>>>((const unsigned int*)adj, W);

    cudaFuncSetAttribute(k_gemm1, cudaFuncAttributeMaxDynamicSharedMemorySize, G1_TOTAL);
    k_gemm1<<<(B * L) / 128, 256, G1_TOTAL>>>(h, a);

    cudaFuncSetAttribute(k_attn, cudaFuncAttributeMaxDynamicSharedMemorySize, SM_TOTAL);
    dim3 grid(L / 128, B);
    k_attn<<<grid, 256, SM_TOTAL>>>(bias, adj, out);
}

// round 10
// speedup vs baseline: 2.7476x; 1.1956x over previous
#include <cuda_runtime.h>
#include <cuda_bf16.h>
#include <cuda_fp16.h>
#include <math.h>
#include <stdint.h>

#define B    128
#define L    512
#define FIN  128
#define FOUT 128
#define ALPHA 0.2f

// Scratch (device globals — no allocation allowed)
__device__ __half g_WhT[(size_t)B * FOUT * L];          // Wh^T fp16: [b][n][l]
__device__ __nv_bfloat16 g_WTh[FOUT * FIN];             // W^T bf16 hi: [n][k]
__device__ __nv_bfloat16 g_WTl[FOUT * FIN];             // W^T bf16 lo
__device__ float g_ei[B * L];
__device__ float g_ej[B * L];
__device__ int   g_maskKind;   // 0=int32, 1=uint8, 2=float32

// ============================ helpers ============================
__device__ __forceinline__ uint32_t smem_u32(const void* p) {
    uint32_t a;
    asm("{ .reg .u64 t; cvta.to.shared.u64 t, %1; cvt.u32.u64 %0, t; }"
        : "=r"(a) : "l"(p));
    return a;
}
__device__ __forceinline__ void ldsm_x4(uint32_t* r, uint32_t addr) {
    asm volatile("ldmatrix.sync.aligned.m8n8.x4.shared.b16 {%0,%1,%2,%3}, [%4];"
                 : "=r"(r[0]), "=r"(r[1]), "=r"(r[2]), "=r"(r[3]) : "r"(addr));
}
__device__ __forceinline__ void mma_bf16(float* c, const uint32_t* a,
                                         uint32_t b0, uint32_t b1) {
    asm volatile(
        "mma.sync.aligned.m16n8k16.row.col.f32.bf16.bf16.f32 "
        "{%0,%1,%2,%3}, {%4,%5,%6,%7}, {%8,%9}, {%0,%1,%2,%3};"
        : "+f"(c[0]), "+f"(c[1]), "+f"(c[2]), "+f"(c[3])
        : "r"(a[0]), "r"(a[1]), "r"(a[2]), "r"(a[3]), "r"(b0), "r"(b1));
}
__device__ __forceinline__ void mma_f16(float* c, const uint32_t* a,
                                        uint32_t b0, uint32_t b1) {
    asm volatile(
        "mma.sync.aligned.m16n8k16.row.col.f32.f16.f16.f32 "
        "{%0,%1,%2,%3}, {%4,%5,%6,%7}, {%8,%9}, {%0,%1,%2,%3};"
        : "+f"(c[0]), "+f"(c[1]), "+f"(c[2]), "+f"(c[3])
        : "r"(a[0]), "r"(a[1]), "r"(a[2]), "r"(a[3]), "r"(b0), "r"(b1));
}
__device__ __forceinline__ uint32_t pack_bf2(__nv_bfloat16 a, __nv_bfloat16 b) {
    return (uint32_t)__bfloat16_as_ushort(a) | ((uint32_t)__bfloat16_as_ushort(b) << 16);
}
__device__ __forceinline__ uint32_t pack_h2(float a, float b) {
    __half2 h = __floats2half2_rn(a, b);
    return *(uint32_t*)&h;
}

// ---------------------------------------------------------------------------
// Kernel 0: mask-layout detect (block 0) + W split/transpose (all 64 blocks)
// ---------------------------------------------------------------------------
__global__ void k_prep(const unsigned int* __restrict__ m,
                       const float* __restrict__ W) {
    if (blockIdx.x == 0 && threadIdx.x < 32) {
        unsigned gt1 = 0, flt = 0;
        for (int i = threadIdx.x; i < 256; i += 32) {
            unsigned w = m[i];
            if (w == 0x3F800000u) flt = 1;
            else if (w > 1u)      gt1 = 1;
        }
        unsigned bft = __ballot_sync(0xFFFFFFFFu, flt);
        unsigned bgt = __ballot_sync(0xFFFFFFFFu, gt1);
        if (threadIdx.x == 0)
            g_maskKind = bft ? 2 : (bgt ? 1 : 0);
    }
    for (int idx = blockIdx.x * blockDim.x + threadIdx.x; idx < FIN * FOUT;
         idx += gridDim.x * blockDim.x) {
        int n = idx >> 7, k = idx & 127;
        float v = W[k * FOUT + n];
        __nv_bfloat16 hi = __float2bfloat16(v);
        __nv_bfloat16 lo = __float2bfloat16(v - __bfloat162float(hi));
        g_WTh[idx] = hi;
        g_WTl[idx] = lo;
    }
}

// ---------------------------------------------------------------------------
// Kernel 1: Wh = h @ W on HMMA (split bf16, 3 chains — Wh/ei/ej need ~1e-5).
// Unchanged from R9 (validated).
// ---------------------------------------------------------------------------
#define G1_AH 0
#define G1_AL 18432
#define G1_WH 36864
#define G1_WL 55296
#define G1_AV 73728
#define G1_TOTAL 74752
#define TSTRIDE 272

__global__ __launch_bounds__(256, 2) void k_gemm1(const float* __restrict__ h,
                                                  const float* __restrict__ a) {
    extern __shared__ char sm[];
    const uint32_t sb = smem_u32(sm);

    const int t    = threadIdx.x;
    const int wid  = t >> 5;
    const int lane = t & 31;
    const long rowBase = (long)blockIdx.x * 128;
    const int  bIdx  = (int)(rowBase >> 9);
    const int  lBase = (int)(rowBase & 511);

    if (t < 64) *(float4*)(sm + G1_AV + t * 16) = *(const float4*)(a + t * 4);

    float acc[16][4];
    #pragma unroll
    for (int n = 0; n < 16; n++)
        #pragma unroll
        for (int c = 0; c < 4; c++) acc[n][c] = 0.f;

    const int aRow  = wid * 16 + (lane & 15);
    const int aKoff = (lane >> 4) * 16;
    const uint32_t aAddrH = sb + G1_AH + aRow * 144 + aKoff;
    const uint32_t aAddrL = sb + G1_AL + aRow * 144 + aKoff;
    const int bRow  = (lane & 7) + ((lane >> 4) << 3);
    const int bKoff = ((lane >> 3) & 1) * 16;
    const uint32_t bAddrH = sb + G1_WH + bRow * 144 + bKoff;
    const uint32_t bAddrL = sb + G1_WL + bRow * 144 + bKoff;

    for (int kc = 0; kc < FIN; kc += 64) {
        __syncthreads();
        #pragma unroll
        for (int i = 0; i < 8; i++) {
            const int idx = t + 256 * i;
            const int mm = idx >> 4, k4 = idx & 15;
            float4 v = *(const float4*)(h + (rowBase + mm) * FIN + kc + k4 * 4);
            __nv_bfloat16 h0 = __float2bfloat16(v.x), h1 = __float2bfloat16(v.y);
            __nv_bfloat16 h2 = __float2bfloat16(v.z), h3 = __float2bfloat16(v.w);
            uint2 hv = {pack_bf2(h0, h1), pack_bf2(h2, h3)};
            uint2 lv = {pack_bf2(__float2bfloat16(v.x - __bfloat162float(h0)),
                                 __float2bfloat16(v.y - __bfloat162float(h1))),
                        pack_bf2(__float2bfloat16(v.z - __bfloat162float(h2)),
                                 __float2bfloat16(v.w - __bfloat162float(h3)))};
            *(uint2*)(sm + G1_AH + mm * 144 + k4 * 8) = hv;
            *(uint2*)(sm + G1_AL + mm * 144 + k4 * 8) = lv;
        }
        #pragma unroll
        for (int i = 0; i < 4; i++) {
            const int idx = t + 256 * i;
            const int n = idx >> 3, c = idx & 7;
            *(uint4*)(sm + G1_WH + n * 144 + c * 16) =
                *(const uint4*)(g_WTh + n * FIN + kc + c * 8);
            *(uint4*)(sm + G1_WL + n * 144 + c * 16) =
                *(const uint4*)(g_WTl + n * FIN + kc + c * 8);
        }
        __syncthreads();

        #pragma unroll
        for (int ks = 0; ks < 4; ks++) {
            uint32_t ah[4], al[4];
            ldsm_x4(ah, aAddrH + ks * 32);
            ldsm_x4(al, aAddrL + ks * 32);
            #pragma unroll
            for (int g = 0; g < 8; g++) {
                uint32_t bh[4], bl[4];
                ldsm_x4(bh, bAddrH + g * 16 * 144 + ks * 32);
                ldsm_x4(bl, bAddrL + g * 16 * 144 + ks * 32);
                mma_bf16(acc[g * 2],     ah, bh[0], bh[1]);
                mma_bf16(acc[g * 2 + 1], ah, bh[2], bh[3]);
                mma_bf16(acc[g * 2],     ah, bl[0], bl[1]);
                mma_bf16(acc[g * 2 + 1], ah, bl[2], bl[3]);
                mma_bf16(acc[g * 2],     al, bh[0], bh[1]);
                mma_bf16(acc[g * 2 + 1], al, bh[2], bh[3]);
            }
        }
    }

    // --- epilogue: ei/ej from fragments ---
    {
        const float* as1 = (const float*)(sm + G1_AV);
        const float* as2 = as1 + 128;
        const int k2 = (lane & 3) * 2;
        float e1a = 0.f, e2a = 0.f, e1b = 0.f, e2b = 0.f;
        #pragma unroll
        for (int nt = 0; nt < 16; nt++) {
            const int c0 = nt * 8 + k2;
            float2 a1v = *(const float2*)&as1[c0];
            float2 a2v = *(const float2*)&as2[c0];
            e1a += acc[nt][0] * a1v.x + acc[nt][1] * a1v.y;
            e2a += acc[nt][0] * a2v.x + acc[nt][1] * a2v.y;
            e1b += acc[nt][2] * a1v.x + acc[nt][3] * a1v.y;
            e2b += acc[nt][2] * a2v.x + acc[nt][3] * a2v.y;
        }
        #pragma unroll
        for (int o = 1; o <= 2; o <<= 1) {
            e1a += __shfl_xor_sync(0xFFFFFFFFu, e1a, o);
            e2a += __shfl_xor_sync(0xFFFFFFFFu, e2a, o);
            e1b += __shfl_xor_sync(0xFFFFFFFFu, e1b, o);
            e2b += __shfl_xor_sync(0xFFFFFFFFu, e2b, o);
        }
        if ((lane & 3) == 0) {
            const int r0 = wid * 16 + (lane >> 2);
            g_ei[rowBase + r0]     = e1a;
            g_ej[rowBase + r0]     = e2a;
            g_ei[rowBase + r0 + 8] = e1b;
            g_ej[rowBase + r0 + 8] = e2b;
        }
    }

    // --- epilogue: stage fp16 WhT [n][m] in smem, coalesced store ---
    __syncthreads();
    char* TH = sm;
    {
        const int r0 = wid * 16 + (lane >> 2);
        const int k2 = (lane & 3) * 2;
        #pragma unroll
        for (int nt = 0; nt < 16; nt++) {
            const int c0 = nt * 8 + k2;
            #pragma unroll
            for (int q = 0; q < 4; q++) {
                const int cc = c0 + (q & 1);
                const int mm = r0 + (q >> 1) * 8;
                *(__half*)(TH + cc * TSTRIDE + mm * 2) = __float2half_rn(acc[nt][q]);
            }
        }
    }
    __syncthreads();
    #pragma unroll
    for (int i = 0; i < 8; i++) {
        const int idx = t + 256 * i;
        const int n = idx >> 4, c = idx & 15;
        const size_t go = ((size_t)bIdx * FOUT + n) * L + lBase + c * 8;
        *(uint4*)(g_WhT + go) = *(uint4*)(TH + n * TSTRIDE + c * 16);
    }
}

// ---------------------------------------------------------------------------
// Kernel 2: fused attention, fp16 HMMA.
//  p-phase R10: warp w owns rows w*16..+15; lane owns cols j0+2l,2l+1 ->
//  fully coalesced bias/adj loads, conflict-free STS. Per-row partial sums
//  stay in registers (sump[16]); ONE smem reduction at kernel end (no
//  in-loop shuffles). B-copy spread over all 8 warps (4 uint4/thread).
// ---------------------------------------------------------------------------
#define SM_PH 0
#define SM_BH 18432
#define SM_EJ 36864   // 512 floats
#define SM_EI 38912   // 128 floats
#define SM_SS 39424   // 128 floats
#define SM_TOTAL 39936

__global__ __launch_bounds__(256, 2) void k_attn(const float* __restrict__ bias,
                                                 const void* __restrict__ adj,
                                                 float* __restrict__ out) {
    extern __shared__ char smem[];
    const uint32_t sb = smem_u32(smem);

    const int t    = threadIdx.x;
    const int wid  = t >> 5;
    const int lane = t & 31;
    const int b    = blockIdx.y;
    const int i0   = blockIdx.x * 128;

    const int kind = g_maskKind;
    const int* adjI = (const int*)adj;
    const unsigned char* adjB = (const unsigned char*)adj;
    const float* adjF = (const float*)adj;

    float* ejs  = (float*)(smem + SM_EJ);
    float* eis  = (float*)(smem + SM_EI);
    float* ssum = (float*)(smem + SM_SS);
    if (t < 128) {
        *(float4*)&ejs[t * 4] = *(const float4*)&g_ej[b * L + t * 4];
        eis[t] = g_ei[b * L + i0 + t];
    }

    float sump[16];
    #pragma unroll
    for (int r = 0; r < 16; r++) sump[r] = 0.f;

    float acc[16][4];
    #pragma unroll
    for (int n = 0; n < 16; n++)
        #pragma unroll
        for (int c = 0; c < 4; c++) acc[n][c] = 0.f;

    const int aRow  = wid * 16 + (lane & 15);
    const int aKoff = (lane >> 4) * 16;
    const uint32_t aAddr = sb + SM_PH + aRow * 144 + aKoff;
    const int bRow  = (lane & 7) + ((lane >> 4) << 3);
    const int bKoff = ((lane >> 3) & 1) * 16;
    const uint32_t bAddr = sb + SM_BH + bRow * 144 + bKoff;

    const int rowM = wid * 16;   // this warp's first p row
    const float* biasBase = bias + ((size_t)b * L + i0 + rowM) * L + 2 * lane;
    const size_t adjBase  = (size_t)(i0 + rowM) * L + 2 * lane;

    __syncthreads();   // eis/ejs visible

    for (int jt = 0; jt < 8; jt++) {
        const int j0 = jt * 64;
        if (jt) __syncthreads();   // previous tile's fragment reads done

        // ---- B copy: 4 uint4 per thread (all warps) ----
        {
            const size_t bbase = (size_t)b * FOUT * L + j0;
            #pragma unroll
            for (int i = 0; i < 4; i++) {
                const int idx = t + 256 * i;
                const int n = idx >> 3, c = idx & 7;
                *(uint4*)(smem + SM_BH + n * 144 + c * 16) =
                    *(const uint4*)(g_WhT + bbase + (size_t)n * L + c * 8);
            }
        }

        // ---- p-phase: 16 rows per warp, 2 cols per lane (coalesced) ----
        {
            const float2 ejv = *(const float2*)&ejs[j0 + 2 * lane];
            const float* bp = biasBase + j0;
            const size_t ap0 = adjBase + j0;
            #pragma unroll
            for (int r = 0; r < 16; r++) {
                const float eim = eis[rowM + r];
                float2 bv = *(const float2*)(bp + (size_t)r * L);
                bool m0, m1;
                if (kind == 0) {
                    int2 w = *(const int2*)(adjI + ap0 + (size_t)r * L);
                    m0 = w.x != 0; m1 = w.y != 0;
                } else if (kind == 2) {
                    float2 w = *(const float2*)(adjF + ap0 + (size_t)r * L);
                    m0 = w.x != 0.f; m1 = w.y != 0.f;
                } else {
                    unsigned short w = *(const unsigned short*)(adjB + ap0 + (size_t)r * L);
                    m0 = (w & 0xFFu) != 0; m1 = (w & 0xFF00u) != 0;
                }
                float x0 = eim + ejv.x;
                float x1 = eim + ejv.y;
                x0 = (x0 > 0.f ? x0 : ALPHA * x0) + bv.x;
                x1 = (x1 > 0.f ? x1 : ALPHA * x1) + bv.y;
                float p0 = m0 ? __expf(x0) : 0.f;
                float p1 = m1 ? __expf(x1) : 0.f;
                sump[r] += p0 + p1;
                *(uint32_t*)(smem + SM_PH + (rowM + r) * 144 + lane * 4) =
                    pack_h2(p0, p1);
            }
        }
        __syncthreads();

        // ---- HMMA phase ----
        #pragma unroll
        for (int ks = 0; ks < 4; ks++) {
            uint32_t ap[4];
            ldsm_x4(ap, aAddr + ks * 32);
            #pragma unroll
            for (int g = 0; g < 8; g++) {
                uint32_t bw[4];
                ldsm_x4(bw, bAddr + g * 16 * 144 + ks * 32);
                mma_f16(acc[g * 2],     ap, bw[0], bw[1]);
                mma_f16(acc[g * 2 + 1], ap, bw[2], bw[3]);
            }
        }
    }

    // ---- one-time row-sum reduction (overlays PH region; MMA is done) ----
    __syncthreads();
    float* red = (float*)(smem + SM_PH);   // [128][33] padded
    #pragma unroll
    for (int r = 0; r < 16; r++)
        red[(rowM + r) * 33 + lane] = sump[r];
    __syncthreads();
    if (t < 128) {
        float s = 0.f;
        #pragma unroll
        for (int k = 0; k < 32; k++) s += red[t * 33 + k];
        ssum[t] = s;
    }
    __syncthreads();

    // ---- epilogue: divide by row sum, ELU, store ----
    const int g  = lane >> 2;
    const int i2 = (lane & 3) * 2;
    const int r0 = wid * 16 + g;
    const int r1 = r0 + 8;
    const float inv0 = 1.f / ssum[r0];
    const float inv1 = 1.f / ssum[r1];
    float* o0 = out + ((size_t)b * L + i0 + r0) * FOUT;
    float* o1 = out + ((size_t)b * L + i0 + r1) * FOUT;
    #pragma unroll
    for (int nt = 0; nt < 16; nt++) {
        float v0 = acc[nt][0] * inv0, v1 = acc[nt][1] * inv0;
        float v2 = acc[nt][2] * inv1, v3 = acc[nt][3] * inv1;
        v0 = v0 > 0.f ? v0 : expm1f(v0);
        v1 = v1 > 0.f ? v1 : expm1f(v1);
        v2 = v2 > 0.f ? v2 : expm1f(v2);
        v3 = v3 > 0.f ? v3 : expm1f(v3);
        float2 w0 = {v0, v1}, w1 = {v2, v3};
        *(float2*)(o0 + nt * 8 + i2) = w0;
        *(float2*)(o1 + nt * 8 + i2) = w1;
    }
}

// ---------------------------------------------------------------------------
extern "C" void kernel_launch(void* const* d_in, const int* in_sizes, int n_in,
                              void* d_out, int out_size) {
    const float* h    = (const float*)d_in[0];
    const float* W    = (const float*)d_in[1];
    const float* a    = (const float*)d_in[2];
    const float* bias = (const float*)d_in[3];
    const void*  adj  = d_in[4];
    float* out = (float*)d_out;

    k_prep<<<64, 256>>>((const unsigned int*)adj, W);

    cudaFuncSetAttribute(k_gemm1, cudaFuncAttributeMaxDynamicSharedMemorySize, G1_TOTAL);
    k_gemm1<<<(B * L) / 128, 256, G1_TOTAL>>>(h, a);

    cudaFuncSetAttribute(k_attn, cudaFuncAttributeMaxDynamicSharedMemorySize, SM_TOTAL);
    dim3 grid(L / 128, B);
    k_attn<<<grid, 256, SM_TOTAL>>>(bias, adj, out);
}

// round 11
// speedup vs baseline: 3.1066x; 1.1307x over previous
#include <cuda_runtime.h>
#include <cuda_bf16.h>
#include <cuda_fp16.h>
#include <math.h>
#include <stdint.h>

#define B    128
#define L    512
#define FIN  128
#define FOUT 128
#define ALPHA 0.2f

// Scratch (device globals — no allocation allowed)
__device__ __half g_WhT[(size_t)B * FOUT * L];          // Wh^T fp16: [b][n][l]
__device__ __nv_bfloat16 g_WTh[FOUT * FIN];             // W^T bf16 hi: [n][k]
__device__ __nv_bfloat16 g_WTl[FOUT * FIN];             // W^T bf16 lo
__device__ float g_ei[B * L];
__device__ float g_ej[B * L];
__device__ uint32_t g_adjBits[512 * 16];                // adj bitmask: row-major, 16 words/row

// ============================ helpers ============================
__device__ __forceinline__ uint32_t smem_u32(const void* p) {
    uint32_t a;
    asm("{ .reg .u64 t; cvta.to.shared.u64 t, %1; cvt.u32.u64 %0, t; }"
        : "=r"(a) : "l"(p));
    return a;
}
__device__ __forceinline__ void ldsm_x4(uint32_t* r, uint32_t addr) {
    asm volatile("ldmatrix.sync.aligned.m8n8.x4.shared.b16 {%0,%1,%2,%3}, [%4];"
                 : "=r"(r[0]), "=r"(r[1]), "=r"(r[2]), "=r"(r[3]) : "r"(addr));
}
__device__ __forceinline__ void mma_bf16(float* c, const uint32_t* a,
                                         uint32_t b0, uint32_t b1) {
    asm volatile(
        "mma.sync.aligned.m16n8k16.row.col.f32.bf16.bf16.f32 "
        "{%0,%1,%2,%3}, {%4,%5,%6,%7}, {%8,%9}, {%0,%1,%2,%3};"
        : "+f"(c[0]), "+f"(c[1]), "+f"(c[2]), "+f"(c[3])
        : "r"(a[0]), "r"(a[1]), "r"(a[2]), "r"(a[3]), "r"(b0), "r"(b1));
}
__device__ __forceinline__ void mma_f16(float* c, const uint32_t* a,
                                        uint32_t b0, uint32_t b1) {
    asm volatile(
        "mma.sync.aligned.m16n8k16.row.col.f32.f16.f16.f32 "
        "{%0,%1,%2,%3}, {%4,%5,%6,%7}, {%8,%9}, {%0,%1,%2,%3};"
        : "+f"(c[0]), "+f"(c[1]), "+f"(c[2]), "+f"(c[3])
        : "r"(a[0]), "r"(a[1]), "r"(a[2]), "r"(a[3]), "r"(b0), "r"(b1));
}
__device__ __forceinline__ uint32_t pack_bf2(__nv_bfloat16 a, __nv_bfloat16 b) {
    return (uint32_t)__bfloat16_as_ushort(a) | ((uint32_t)__bfloat16_as_ushort(b) << 16);
}
__device__ __forceinline__ uint32_t pack_h2(float a, float b) {
    __half2 h = __floats2half2_rn(a, b);
    return *(uint32_t*)&h;
}
#define CP_ASYNC16(dst, src) \
    asm volatile("cp.async.cg.shared.global [%0], [%1], 16;" \
                 :: "r"(dst), "l"(src) : "memory")
#define CP_COMMIT() asm volatile("cp.async.commit_group;" ::: "memory")
#define CP_WAIT1()  asm volatile("cp.async.wait_group 1;" ::: "memory")
#define CP_WAIT0()  asm volatile("cp.async.wait_group 0;" ::: "memory")

// ---------------------------------------------------------------------------
// Kernel 0 (grid = 64 x 256): block-local mask-kind detect, W split/transpose,
// adj -> bitmask (one warp per row via ballot).
// ---------------------------------------------------------------------------
__global__ void k_prep(const unsigned int* __restrict__ m,
                       const float* __restrict__ W) {
    __shared__ int sgt1, sflt;
    const int t = threadIdx.x;
    if (t == 0) { sgt1 = 0; sflt = 0; }
    __syncthreads();
    {
        unsigned w = m[t];                 // first 1KB scan (diag guarantees a hit)
        if (w == 0x3F800000u) atomicOr(&sflt, 1);
        else if (w > 1u)      atomicOr(&sgt1, 1);
    }
    __syncthreads();
    const int kind = sflt ? 2 : (sgt1 ? 1 : 0);   // 0=int32, 1=uint8, 2=float32

    // W split/transpose
    for (int idx = blockIdx.x * blockDim.x + t; idx < FIN * FOUT;
         idx += gridDim.x * blockDim.x) {
        int n = idx >> 7, k = idx & 127;
        float v = W[k * FOUT + n];
        __nv_bfloat16 hi = __float2bfloat16(v);
        __nv_bfloat16 lo = __float2bfloat16(v - __bfloat162float(hi));
        g_WTh[idx] = hi;
        g_WTl[idx] = lo;
    }

    // adj bitmask: warp (blockIdx.x*8 + wid) owns row, 16 words of 32 bits
    const int wid = t >> 5, lane = t & 31;
    const int row = blockIdx.x * 8 + wid;          // 64*8 = 512 rows
    const int* adjI = (const int*)m;
    const unsigned char* adjB = (const unsigned char*)m;
    const float* adjF = (const float*)m;
    #pragma unroll
    for (int w = 0; w < 16; w++) {
        const int e = row * 512 + w * 32 + lane;
        bool v;
        if (kind == 0)      v = adjI[e] != 0;
        else if (kind == 1) v = adjB[e] != 0;
        else                v = adjF[e] != 0.f;
        unsigned word = __ballot_sync(0xFFFFFFFFu, v);
        if (lane == 0) g_adjBits[row * 16 + w] = word;
    }
}

// ---------------------------------------------------------------------------
// Kernel 1: Wh = h @ W on HMMA (split bf16, 3 chains). Unchanged (validated).
// ---------------------------------------------------------------------------
#define G1_AH 0
#define G1_AL 18432
#define G1_WH 36864
#define G1_WL 55296
#define G1_AV 73728
#define G1_TOTAL 74752
#define TSTRIDE 272

__global__ __launch_bounds__(256, 2) void k_gemm1(const float* __restrict__ h,
                                                  const float* __restrict__ a) {
    extern __shared__ char sm[];
    const uint32_t sb = smem_u32(sm);

    const int t    = threadIdx.x;
    const int wid  = t >> 5;
    const int lane = t & 31;
    const long rowBase = (long)blockIdx.x * 128;
    const int  bIdx  = (int)(rowBase >> 9);
    const int  lBase = (int)(rowBase & 511);

    if (t < 64) *(float4*)(sm + G1_AV + t * 16) = *(const float4*)(a + t * 4);

    float acc[16][4];
    #pragma unroll
    for (int n = 0; n < 16; n++)
        #pragma unroll
        for (int c = 0; c < 4; c++) acc[n][c] = 0.f;

    const int aRow  = wid * 16 + (lane & 15);
    const int aKoff = (lane >> 4) * 16;
    const uint32_t aAddrH = sb + G1_AH + aRow * 144 + aKoff;
    const uint32_t aAddrL = sb + G1_AL + aRow * 144 + aKoff;
    const int bRow  = (lane & 7) + ((lane >> 4) << 3);
    const int bKoff = ((lane >> 3) & 1) * 16;
    const uint32_t bAddrH = sb + G1_WH + bRow * 144 + bKoff;
    const uint32_t bAddrL = sb + G1_WL + bRow * 144 + bKoff;

    for (int kc = 0; kc < FIN; kc += 64) {
        __syncthreads();
        #pragma unroll
        for (int i = 0; i < 8; i++) {
            const int idx = t + 256 * i;
            const int mm = idx >> 4, k4 = idx & 15;
            float4 v = *(const float4*)(h + (rowBase + mm) * FIN + kc + k4 * 4);
            __nv_bfloat16 h0 = __float2bfloat16(v.x), h1 = __float2bfloat16(v.y);
            __nv_bfloat16 h2 = __float2bfloat16(v.z), h3 = __float2bfloat16(v.w);
            uint2 hv = {pack_bf2(h0, h1), pack_bf2(h2, h3)};
            uint2 lv = {pack_bf2(__float2bfloat16(v.x - __bfloat162float(h0)),
                                 __float2bfloat16(v.y - __bfloat162float(h1))),
                        pack_bf2(__float2bfloat16(v.z - __bfloat162float(h2)),
                                 __float2bfloat16(v.w - __bfloat162float(h3)))};
            *(uint2*)(sm + G1_AH + mm * 144 + k4 * 8) = hv;
            *(uint2*)(sm + G1_AL + mm * 144 + k4 * 8) = lv;
        }
        #pragma unroll
        for (int i = 0; i < 4; i++) {
            const int idx = t + 256 * i;
            const int n = idx >> 3, c = idx & 7;
            *(uint4*)(sm + G1_WH + n * 144 + c * 16) =
                *(const uint4*)(g_WTh + n * FIN + kc + c * 8);
            *(uint4*)(sm + G1_WL + n * 144 + c * 16) =
                *(const uint4*)(g_WTl + n * FIN + kc + c * 8);
        }
        __syncthreads();

        #pragma unroll
        for (int ks = 0; ks < 4; ks++) {
            uint32_t ah[4], al[4];
            ldsm_x4(ah, aAddrH + ks * 32);
            ldsm_x4(al, aAddrL + ks * 32);
            #pragma unroll
            for (int g = 0; g < 8; g++) {
                uint32_t bh[4], bl[4];
                ldsm_x4(bh, bAddrH + g * 16 * 144 + ks * 32);
                ldsm_x4(bl, bAddrL + g * 16 * 144 + ks * 32);
                mma_bf16(acc[g * 2],     ah, bh[0], bh[1]);
                mma_bf16(acc[g * 2 + 1], ah, bh[2], bh[3]);
                mma_bf16(acc[g * 2],     ah, bl[0], bl[1]);
                mma_bf16(acc[g * 2 + 1], ah, bl[2], bl[3]);
                mma_bf16(acc[g * 2],     al, bh[0], bh[1]);
                mma_bf16(acc[g * 2 + 1], al, bh[2], bh[3]);
            }
        }
    }

    // --- epilogue: ei/ej from fragments ---
    {
        const float* as1 = (const float*)(sm + G1_AV);
        const float* as2 = as1 + 128;
        const int k2 = (lane & 3) * 2;
        float e1a = 0.f, e2a = 0.f, e1b = 0.f, e2b = 0.f;
        #pragma unroll
        for (int nt = 0; nt < 16; nt++) {
            const int c0 = nt * 8 + k2;
            float2 a1v = *(const float2*)&as1[c0];
            float2 a2v = *(const float2*)&as2[c0];
            e1a += acc[nt][0] * a1v.x + acc[nt][1] * a1v.y;
            e2a += acc[nt][0] * a2v.x + acc[nt][1] * a2v.y;
            e1b += acc[nt][2] * a1v.x + acc[nt][3] * a1v.y;
            e2b += acc[nt][2] * a2v.x + acc[nt][3] * a2v.y;
        }
        #pragma unroll
        for (int o = 1; o <= 2; o <<= 1) {
            e1a += __shfl_xor_sync(0xFFFFFFFFu, e1a, o);
            e2a += __shfl_xor_sync(0xFFFFFFFFu, e2a, o);
            e1b += __shfl_xor_sync(0xFFFFFFFFu, e1b, o);
            e2b += __shfl_xor_sync(0xFFFFFFFFu, e2b, o);
        }
        if ((lane & 3) == 0) {
            const int r0 = wid * 16 + (lane >> 2);
            g_ei[rowBase + r0]     = e1a;
            g_ej[rowBase + r0]     = e2a;
            g_ei[rowBase + r0 + 8] = e1b;
            g_ej[rowBase + r0 + 8] = e2b;
        }
    }

    // --- epilogue: stage fp16 WhT [n][m] in smem, coalesced store ---
    __syncthreads();
    char* TH = sm;
    {
        const int r0 = wid * 16 + (lane >> 2);
        const int k2 = (lane & 3) * 2;
        #pragma unroll
        for (int nt = 0; nt < 16; nt++) {
            const int c0 = nt * 8 + k2;
            #pragma unroll
            for (int q = 0; q < 4; q++) {
                const int cc = c0 + (q & 1);
                const int mm = r0 + (q >> 1) * 8;
                *(__half*)(TH + cc * TSTRIDE + mm * 2) = __float2half_rn(acc[nt][q]);
            }
        }
    }
    __syncthreads();
    #pragma unroll
    for (int i = 0; i < 8; i++) {
        const int idx = t + 256 * i;
        const int n = idx >> 4, c = idx & 15;
        const size_t go = ((size_t)bIdx * FOUT + n) * L + lBase + c * 8;
        *(uint4*)(g_WhT + go) = *(uint4*)(TH + n * TSTRIDE + c * 16);
    }
}

// ---------------------------------------------------------------------------
// Kernel 2: fused attention, fp16 HMMA, cp.async double-buffered bias,
// smem adj bitmask (loaded once).
// ---------------------------------------------------------------------------
#define SM_PH   0        // 18432
#define SM_BH   18432    // 18432
#define SM_BIAS 36864    // 2 x 32768
#define SM_ADJ  102400   // 8192
#define SM_EJ   110592   // 2048
#define SM_EI   112640   // 512
#define SM_SS   113152   // 512
#define SM_TOTAL 113664

__global__ __launch_bounds__(256, 2) void k_attn(const float* __restrict__ bias,
                                                 float* __restrict__ out) {
    extern __shared__ char smem[];
    const uint32_t sb = smem_u32(smem);

    const int t    = threadIdx.x;
    const int wid  = t >> 5;
    const int lane = t & 31;
    const int b    = blockIdx.y;
    const int i0   = blockIdx.x * 128;

    float* ejs  = (float*)(smem + SM_EJ);
    float* eis  = (float*)(smem + SM_EI);
    float* ssum = (float*)(smem + SM_SS);
    uint32_t* adjS = (uint32_t*)(smem + SM_ADJ);

    if (t < 128) {
        *(float4*)&ejs[t * 4] = *(const float4*)&g_ej[b * L + t * 4];
        eis[t] = g_ei[b * L + i0 + t];
    }
    // adj bits for this i-tile: 128 rows x 16 words
    #pragma unroll
    for (int i = 0; i < 8; i++) {
        const int idx = t + 256 * i;
        adjS[idx] = g_adjBits[(i0 + (idx >> 4)) * 16 + (idx & 15)];
    }

    const size_t biasCta = ((size_t)b * L + i0) * L;   // float index
    // prologue: tile 0 -> buf 0
    {
        const uint32_t d0 = sb + SM_BIAS;
        #pragma unroll
        for (int i = 0; i < 8; i++) {
            const int idx = t + 256 * i;
            const int row = idx >> 4, c = idx & 15;
            CP_ASYNC16(d0 + row * 256 + c * 16,
                       bias + biasCta + (size_t)row * L + c * 4);
        }
        CP_COMMIT();
    }

    float sump[16];
    #pragma unroll
    for (int r = 0; r < 16; r++) sump[r] = 0.f;

    float acc[16][4];
    #pragma unroll
    for (int n = 0; n < 16; n++)
        #pragma unroll
        for (int c = 0; c < 4; c++) acc[n][c] = 0.f;

    const int aRow  = wid * 16 + (lane & 15);
    const int aKoff = (lane >> 4) * 16;
    const uint32_t aAddr = sb + SM_PH + aRow * 144 + aKoff;
    const int bRow  = (lane & 7) + ((lane >> 4) << 3);
    const int bKoff = ((lane >> 3) & 1) * 16;
    const uint32_t bAddr = sb + SM_BH + bRow * 144 + bKoff;

    const int rowM   = wid * 16;
    const int bitpos = (2 * lane) & 31;
    const int wadd   = lane >> 4;

    for (int jt = 0; jt < 8; jt++) {
        // issue next tile's bias into the other buffer
        if (jt < 7) {
            const uint32_t d0 = sb + SM_BIAS + ((jt + 1) & 1) * 32768;
            const size_t srcB = biasCta + (size_t)(jt + 1) * 64;
            #pragma unroll
            for (int i = 0; i < 8; i++) {
                const int idx = t + 256 * i;
                const int row = idx >> 4, c = idx & 15;
                CP_ASYNC16(d0 + row * 256 + c * 16,
                           bias + srcB + (size_t)row * L + c * 4);
            }
            CP_COMMIT();
            CP_WAIT1();
        } else {
            CP_WAIT0();
        }
        __syncthreads();   // bias buf[jt&1] visible; prev tile's smem reads done

        // ---- B copy: 4 uint4 per thread ----
        {
            const size_t bbase = (size_t)b * FOUT * L + jt * 64;
            #pragma unroll
            for (int i = 0; i < 4; i++) {
                const int idx = t + 256 * i;
                const int n = idx >> 3, c = idx & 7;
                *(uint4*)(smem + SM_BH + n * 144 + c * 16) =
                    *(const uint4*)(g_WhT + bbase + (size_t)n * L + c * 8);
            }
        }

        // ---- p-phase: bias from smem, mask from bitmask ----
        {
            const float* bsm = (const float*)(smem + SM_BIAS + (jt & 1) * 32768);
            const float2 ejv = *(const float2*)&ejs[jt * 64 + 2 * lane];
            const int wbase = jt * 2 + wadd;
            #pragma unroll
            for (int r = 0; r < 16; r++) {
                const int m = rowM + r;
                const float eim = eis[m];
                float2 bv = *(const float2*)&bsm[m * 64 + 2 * lane];
                const uint32_t word = adjS[m * 16 + wbase];
                const bool m0 = (word >> bitpos) & 1u;
                const bool m1 = (word >> (bitpos + 1)) & 1u;
                float x0 = eim + ejv.x;
                float x1 = eim + ejv.y;
                x0 = (x0 > 0.f ? x0 : ALPHA * x0) + bv.x;
                x1 = (x1 > 0.f ? x1 : ALPHA * x1) + bv.y;
                float p0 = m0 ? __expf(x0) : 0.f;
                float p1 = m1 ? __expf(x1) : 0.f;
                sump[r] += p0 + p1;
                *(uint32_t*)(smem + SM_PH + m * 144 + lane * 4) = pack_h2(p0, p1);
            }
        }
        __syncthreads();

        // ---- HMMA phase ----
        #pragma unroll
        for (int ks = 0; ks < 4; ks++) {
            uint32_t ap[4];
            ldsm_x4(ap, aAddr + ks * 32);
            #pragma unroll
            for (int g = 0; g < 8; g++) {
                uint32_t bw[4];
                ldsm_x4(bw, bAddr + g * 16 * 144 + ks * 32);
                mma_f16(acc[g * 2],     ap, bw[0], bw[1]);
                mma_f16(acc[g * 2 + 1], ap, bw[2], bw[3]);
            }
        }
    }

    // ---- one-time row-sum reduction (overlays PH region; MMA is done) ----
    __syncthreads();
    float* red = (float*)(smem + SM_PH);   // [128][33] padded
    #pragma unroll
    for (int r = 0; r < 16; r++)
        red[(rowM + r) * 33 + lane] = sump[r];
    __syncthreads();
    if (t < 128) {
        float s = 0.f;
        #pragma unroll
        for (int k = 0; k < 32; k++) s += red[t * 33 + k];
        ssum[t] = s;
    }
    __syncthreads();

    // ---- epilogue: divide by row sum, ELU, store ----
    const int g  = lane >> 2;
    const int i2 = (lane & 3) * 2;
    const int r0 = wid * 16 + g;
    const int r1 = r0 + 8;
    const float inv0 = 1.f / ssum[r0];
    const float inv1 = 1.f / ssum[r1];
    float* o0 = out + ((size_t)b * L + i0 + r0) * FOUT;
    float* o1 = out + ((size_t)b * L + i0 + r1) * FOUT;
    #pragma unroll
    for (int nt = 0; nt < 16; nt++) {
        float v0 = acc[nt][0] * inv0, v1 = acc[nt][1] * inv0;
        float v2 = acc[nt][2] * inv1, v3 = acc[nt][3] * inv1;
        v0 = v0 > 0.f ? v0 : expm1f(v0);
        v1 = v1 > 0.f ? v1 : expm1f(v1);
        v2 = v2 > 0.f ? v2 : expm1f(v2);
        v3 = v3 > 0.f ? v3 : expm1f(v3);
        float2 w0 = {v0, v1}, w1 = {v2, v3};
        *(float2*)(o0 + nt * 8 + i2) = w0;
        *(float2*)(o1 + nt * 8 + i2) = w1;
    }
}

// ---------------------------------------------------------------------------
extern "C" void kernel_launch(void* const* d_in, const int* in_sizes, int n_in,
                              void* d_out, int out_size) {
    const float* h    = (const float*)d_in[0];
    const float* W    = (const float*)d_in[1];
    const float* a    = (const float*)d_in[2];
    const float* bias = (const float*)d_in[3];
    const void*  adj  = d_in[4];
    float* out = (float*)d_out;

    k_prep<<<64, 256>>>((const unsigned int*)adj, W);

    cudaFuncSetAttribute(k_gemm1, cudaFuncAttributeMaxDynamicSharedMemorySize, G1_TOTAL);
    k_gemm1<<<(B * L) / 128, 256, G1_TOTAL>>>(h, a);

    cudaFuncSetAttribute(k_attn, cudaFuncAttributeMaxDynamicSharedMemorySize, SM_TOTAL);
    dim3 grid(L / 128, B);
    k_attn<<<grid, 256, SM_TOTAL>>>(bias, out);
}

// round 12
// speedup vs baseline: 3.6242x; 1.1666x over previous
#include <cuda_runtime.h>
#include <cuda_bf16.h>
#include <cuda_fp16.h>
#include <math.h>
#include <stdint.h>

#define B    128
#define L    512
#define FIN  128
#define FOUT 128
#define ALPHA 0.2f

// Scratch (device globals — no allocation allowed)
__device__ __half g_WhT[(size_t)B * FOUT * L];          // Wh^T fp16: [b][n][l]
__device__ __nv_bfloat16 g_WTh[FOUT * FIN];             // W^T bf16 hi: [n][k]
__device__ __nv_bfloat16 g_WTl[FOUT * FIN];             // W^T bf16 lo
__device__ float g_ei[B * L];
__device__ float g_ej[B * L];
__device__ uint32_t g_adjBits[512 * 16];                // adj bitmask

// ============================ helpers ============================
__device__ __forceinline__ uint32_t smem_u32(const void* p) {
    uint32_t a;
    asm("{ .reg .u64 t; cvta.to.shared.u64 t, %1; cvt.u32.u64 %0, t; }"
        : "=r"(a) : "l"(p));
    return a;
}
__device__ __forceinline__ void ldsm_x4(uint32_t* r, uint32_t addr) {
    asm volatile("ldmatrix.sync.aligned.m8n8.x4.shared.b16 {%0,%1,%2,%3}, [%4];"
                 : "=r"(r[0]), "=r"(r[1]), "=r"(r[2]), "=r"(r[3]) : "r"(addr));
}
__device__ __forceinline__ void mma_bf16(float* c, const uint32_t* a,
                                         uint32_t b0, uint32_t b1) {
    asm volatile(
        "mma.sync.aligned.m16n8k16.row.col.f32.bf16.bf16.f32 "
        "{%0,%1,%2,%3}, {%4,%5,%6,%7}, {%8,%9}, {%0,%1,%2,%3};"
        : "+f"(c[0]), "+f"(c[1]), "+f"(c[2]), "+f"(c[3])
        : "r"(a[0]), "r"(a[1]), "r"(a[2]), "r"(a[3]), "r"(b0), "r"(b1));
}
__device__ __forceinline__ void mma_f16(float* c, const uint32_t* a,
                                        uint32_t b0, uint32_t b1) {
    asm volatile(
        "mma.sync.aligned.m16n8k16.row.col.f32.f16.f16.f32 "
        "{%0,%1,%2,%3}, {%4,%5,%6,%7}, {%8,%9}, {%0,%1,%2,%3};"
        : "+f"(c[0]), "+f"(c[1]), "+f"(c[2]), "+f"(c[3])
        : "r"(a[0]), "r"(a[1]), "r"(a[2]), "r"(a[3]), "r"(b0), "r"(b1));
}
__device__ __forceinline__ uint32_t pack_bf2(__nv_bfloat16 a, __nv_bfloat16 b) {
    return (uint32_t)__bfloat16_as_ushort(a) | ((uint32_t)__bfloat16_as_ushort(b) << 16);
}
__device__ __forceinline__ uint32_t pack_h2(float a, float b) {
    __half2 h = __floats2half2_rn(a, b);
    return *(uint32_t*)&h;
}
#define CP_ASYNC16(dst, src) \
    asm volatile("cp.async.cg.shared.global [%0], [%1], 16;" \
                 :: "r"(dst), "l"(src) : "memory")
#define CP_COMMIT() asm volatile("cp.async.commit_group;" ::: "memory")
#define CP_WAIT(n)  asm volatile("cp.async.wait_group %0;" :: "n"(n) : "memory")

// ---------------------------------------------------------------------------
// Kernel 0: mask-kind detect (block-local), W split/transpose, adj -> bitmask
// ---------------------------------------------------------------------------
__global__ void k_prep(const unsigned int* __restrict__ m,
                       const float* __restrict__ W) {
    __shared__ int sgt1, sflt;
    const int t = threadIdx.x;
    if (t == 0) { sgt1 = 0; sflt = 0; }
    __syncthreads();
    {
        unsigned w = m[t];
        if (w == 0x3F800000u) atomicOr(&sflt, 1);
        else if (w > 1u)      atomicOr(&sgt1, 1);
    }
    __syncthreads();
    const int kind = sflt ? 2 : (sgt1 ? 1 : 0);

    for (int idx = blockIdx.x * blockDim.x + t; idx < FIN * FOUT;
         idx += gridDim.x * blockDim.x) {
        int n = idx >> 7, k = idx & 127;
        float v = W[k * FOUT + n];
        __nv_bfloat16 hi = __float2bfloat16(v);
        __nv_bfloat16 lo = __float2bfloat16(v - __bfloat162float(hi));
        g_WTh[idx] = hi;
        g_WTl[idx] = lo;
    }

    const int wid = t >> 5, lane = t & 31;
    const int row = blockIdx.x * 8 + wid;
    const int* adjI = (const int*)m;
    const unsigned char* adjB = (const unsigned char*)m;
    const float* adjF = (const float*)m;
    #pragma unroll
    for (int w = 0; w < 16; w++) {
        const int e = row * 512 + w * 32 + lane;
        bool v;
        if (kind == 0)      v = adjI[e] != 0;
        else if (kind == 1) v = adjB[e] != 0;
        else                v = adjF[e] != 0.f;
        unsigned word = __ballot_sync(0xFFFFFFFFu, v);
        if (lane == 0) g_adjBits[row * 16 + w] = word;
    }
}

// ---------------------------------------------------------------------------
// Kernel 1: Wh = h @ W on HMMA (split bf16, 3 chains). Unchanged (validated).
// ---------------------------------------------------------------------------
#define G1_AH 0
#define G1_AL 18432
#define G1_WH 36864
#define G1_WL 55296
#define G1_AV 73728
#define G1_TOTAL 74752
#define TSTRIDE 272

__global__ __launch_bounds__(256, 2) void k_gemm1(const float* __restrict__ h,
                                                  const float* __restrict__ a) {
    extern __shared__ char sm[];
    const uint32_t sb = smem_u32(sm);

    const int t    = threadIdx.x;
    const int wid  = t >> 5;
    const int lane = t & 31;
    const long rowBase = (long)blockIdx.x * 128;
    const int  bIdx  = (int)(rowBase >> 9);
    const int  lBase = (int)(rowBase & 511);

    if (t < 64) *(float4*)(sm + G1_AV + t * 16) = *(const float4*)(a + t * 4);

    float acc[16][4];
    #pragma unroll
    for (int n = 0; n < 16; n++)
        #pragma unroll
        for (int c = 0; c < 4; c++) acc[n][c] = 0.f;

    const int aRow  = wid * 16 + (lane & 15);
    const int aKoff = (lane >> 4) * 16;
    const uint32_t aAddrH = sb + G1_AH + aRow * 144 + aKoff;
    const uint32_t aAddrL = sb + G1_AL + aRow * 144 + aKoff;
    const int bRow  = (lane & 7) + ((lane >> 4) << 3);
    const int bKoff = ((lane >> 3) & 1) * 16;
    const uint32_t bAddrH = sb + G1_WH + bRow * 144 + bKoff;
    const uint32_t bAddrL = sb + G1_WL + bRow * 144 + bKoff;

    for (int kc = 0; kc < FIN; kc += 64) {
        __syncthreads();
        #pragma unroll
        for (int i = 0; i < 8; i++) {
            const int idx = t + 256 * i;
            const int mm = idx >> 4, k4 = idx & 15;
            float4 v = *(const float4*)(h + (rowBase + mm) * FIN + kc + k4 * 4);
            __nv_bfloat16 h0 = __float2bfloat16(v.x), h1 = __float2bfloat16(v.y);
            __nv_bfloat16 h2 = __float2bfloat16(v.z), h3 = __float2bfloat16(v.w);
            uint2 hv = {pack_bf2(h0, h1), pack_bf2(h2, h3)};
            uint2 lv = {pack_bf2(__float2bfloat16(v.x - __bfloat162float(h0)),
                                 __float2bfloat16(v.y - __bfloat162float(h1))),
                        pack_bf2(__float2bfloat16(v.z - __bfloat162float(h2)),
                                 __float2bfloat16(v.w - __bfloat162float(h3)))};
            *(uint2*)(sm + G1_AH + mm * 144 + k4 * 8) = hv;
            *(uint2*)(sm + G1_AL + mm * 144 + k4 * 8) = lv;
        }
        #pragma unroll
        for (int i = 0; i < 4; i++) {
            const int idx = t + 256 * i;
            const int n = idx >> 3, c = idx & 7;
            *(uint4*)(sm + G1_WH + n * 144 + c * 16) =
                *(const uint4*)(g_WTh + n * FIN + kc + c * 8);
            *(uint4*)(sm + G1_WL + n * 144 + c * 16) =
                *(const uint4*)(g_WTl + n * FIN + kc + c * 8);
        }
        __syncthreads();

        #pragma unroll
        for (int ks = 0; ks < 4; ks++) {
            uint32_t ah[4], al[4];
            ldsm_x4(ah, aAddrH + ks * 32);
            ldsm_x4(al, aAddrL + ks * 32);
            #pragma unroll
            for (int g = 0; g < 8; g++) {
                uint32_t bh[4], bl[4];
                ldsm_x4(bh, bAddrH + g * 16 * 144 + ks * 32);
                ldsm_x4(bl, bAddrL + g * 16 * 144 + ks * 32);
                mma_bf16(acc[g * 2],     ah, bh[0], bh[1]);
                mma_bf16(acc[g * 2 + 1], ah, bh[2], bh[3]);
                mma_bf16(acc[g * 2],     ah, bl[0], bl[1]);
                mma_bf16(acc[g * 2 + 1], ah, bl[2], bl[3]);
                mma_bf16(acc[g * 2],     al, bh[0], bh[1]);
                mma_bf16(acc[g * 2 + 1], al, bh[2], bh[3]);
            }
        }
    }

    {
        const float* as1 = (const float*)(sm + G1_AV);
        const float* as2 = as1 + 128;
        const int k2 = (lane & 3) * 2;
        float e1a = 0.f, e2a = 0.f, e1b = 0.f, e2b = 0.f;
        #pragma unroll
        for (int nt = 0; nt < 16; nt++) {
            const int c0 = nt * 8 + k2;
            float2 a1v = *(const float2*)&as1[c0];
            float2 a2v = *(const float2*)&as2[c0];
            e1a += acc[nt][0] * a1v.x + acc[nt][1] * a1v.y;
            e2a += acc[nt][0] * a2v.x + acc[nt][1] * a2v.y;
            e1b += acc[nt][2] * a1v.x + acc[nt][3] * a1v.y;
            e2b += acc[nt][2] * a2v.x + acc[nt][3] * a2v.y;
        }
        #pragma unroll
        for (int o = 1; o <= 2; o <<= 1) {
            e1a += __shfl_xor_sync(0xFFFFFFFFu, e1a, o);
            e2a += __shfl_xor_sync(0xFFFFFFFFu, e2a, o);
            e1b += __shfl_xor_sync(0xFFFFFFFFu, e1b, o);
            e2b += __shfl_xor_sync(0xFFFFFFFFu, e2b, o);
        }
        if ((lane & 3) == 0) {
            const int r0 = wid * 16 + (lane >> 2);
            g_ei[rowBase + r0]     = e1a;
            g_ej[rowBase + r0]     = e2a;
            g_ei[rowBase + r0 + 8] = e1b;
            g_ej[rowBase + r0 + 8] = e2b;
        }
    }

    __syncthreads();
    char* TH = sm;
    {
        const int r0 = wid * 16 + (lane >> 2);
        const int k2 = (lane & 3) * 2;
        #pragma unroll
        for (int nt = 0; nt < 16; nt++) {
            const int c0 = nt * 8 + k2;
            #pragma unroll
            for (int q = 0; q < 4; q++) {
                const int cc = c0 + (q & 1);
                const int mm = r0 + (q >> 1) * 8;
                *(__half*)(TH + cc * TSTRIDE + mm * 2) = __float2half_rn(acc[nt][q]);
            }
        }
    }
    __syncthreads();
    #pragma unroll
    for (int i = 0; i < 8; i++) {
        const int idx = t + 256 * i;
        const int n = idx >> 4, c = idx & 15;
        const size_t go = ((size_t)bIdx * FOUT + n) * L + lBase + c * 8;
        *(uint4*)(g_WhT + go) = *(uint4*)(TH + n * TSTRIDE + c * 16);
    }
}

// ---------------------------------------------------------------------------
// Kernel 2: fused attention, fp16 HMMA. Full cp.async pipeline:
//   bias(jt+1) prefetched one tile ahead (double buffer);
//   B(jt) streamed in its own group DURING the p-phase (hidden latency).
// Per tile: sync | commit B(jt), commit bias(jt+1) | wait<=2, sync, p-phase |
//           wait<=1, sync, MMA.
// ---------------------------------------------------------------------------
#define SM_PH   0        // 18432
#define SM_BH   18432    // 18432
#define SM_BIAS 36864    // 2 x 32768
#define SM_ADJ  102400   // 8192
#define SM_EJ   110592   // 2048
#define SM_EI   112640   // 512
#define SM_SS   113152   // 512
#define SM_TOTAL 113664

__global__ __launch_bounds__(256, 2) void k_attn(const float* __restrict__ bias,
                                                 float* __restrict__ out) {
    extern __shared__ char smem[];
    const uint32_t sb = smem_u32(smem);

    const int t    = threadIdx.x;
    const int wid  = t >> 5;
    const int lane = t & 31;
    const int b    = blockIdx.y;
    const int i0   = blockIdx.x * 128;

    float* ejs  = (float*)(smem + SM_EJ);
    float* eis  = (float*)(smem + SM_EI);
    float* ssum = (float*)(smem + SM_SS);
    uint32_t* adjS = (uint32_t*)(smem + SM_ADJ);

    if (t < 128) {
        *(float4*)&ejs[t * 4] = *(const float4*)&g_ej[b * L + t * 4];
        eis[t] = g_ei[b * L + i0 + t];
    }
    #pragma unroll
    for (int i = 0; i < 8; i++) {
        const int idx = t + 256 * i;
        adjS[idx] = g_adjBits[(i0 + (idx >> 4)) * 16 + (idx & 15)];
    }

    const size_t biasCta = ((size_t)b * L + i0) * L;
    const size_t whtCta  = (size_t)b * FOUT * L;

    // prologue: bias(0) -> buf 0  [group]
    {
        const uint32_t d0 = sb + SM_BIAS;
        #pragma unroll
        for (int i = 0; i < 8; i++) {
            const int idx = t + 256 * i;
            const int row = idx >> 4, c = idx & 15;
            CP_ASYNC16(d0 + row * 256 + c * 16,
                       bias + biasCta + (size_t)row * L + c * 4);
        }
        CP_COMMIT();
    }

    float sump[16];
    #pragma unroll
    for (int r = 0; r < 16; r++) sump[r] = 0.f;

    float acc[16][4];
    #pragma unroll
    for (int n = 0; n < 16; n++)
        #pragma unroll
        for (int c = 0; c < 4; c++) acc[n][c] = 0.f;

    const int aRow  = wid * 16 + (lane & 15);
    const int aKoff = (lane >> 4) * 16;
    const uint32_t aAddr = sb + SM_PH + aRow * 144 + aKoff;
    const int bRow  = (lane & 7) + ((lane >> 4) << 3);
    const int bKoff = ((lane >> 3) & 1) * 16;
    const uint32_t bAddr = sb + SM_BH + bRow * 144 + bKoff;

    const int rowM   = wid * 16;
    const int bitpos = (2 * lane) & 31;
    const int wadd   = lane >> 4;

    for (int jt = 0; jt < 8; jt++) {
        __syncthreads();   // MMA(jt-1) finished reading BH/PH in all warps

        // ---- B(jt) -> BH via cp.async (own group; completes during p-phase)
        {
            const size_t bbase = whtCta + (size_t)jt * 64;
            #pragma unroll
            for (int i = 0; i < 4; i++) {
                const int idx = t + 256 * i;
                const int n = idx >> 3, c = idx & 7;
                CP_ASYNC16(sb + SM_BH + n * 144 + c * 16,
                           g_WhT + bbase + (size_t)n * L + c * 8);
            }
            CP_COMMIT();
        }
        // ---- bias(jt+1) -> other buffer
        if (jt < 7) {
            const uint32_t d0 = sb + SM_BIAS + ((jt + 1) & 1) * 32768;
            const size_t srcB = biasCta + (size_t)(jt + 1) * 64;
            #pragma unroll
            for (int i = 0; i < 8; i++) {
                const int idx = t + 256 * i;
                const int row = idx >> 4, c = idx & 15;
                CP_ASYNC16(d0 + row * 256 + c * 16,
                           bias + srcB + (size_t)row * L + c * 4);
            }
            CP_COMMIT();
            CP_WAIT(2);    // bias(jt) complete; B(jt), bias(jt+1) may pend
        } else {
            CP_WAIT(1);    // bias(7) complete; B(7) may pend
        }
        __syncthreads();   // bias buf visible to all threads

        // ---- p-phase (reads bias smem + adj bits; writes PH) ----
        {
            const float* bsm = (const float*)(smem + SM_BIAS + (jt & 1) * 32768);
            const float2 ejv = *(const float2*)&ejs[jt * 64 + 2 * lane];
            const int wbase = jt * 2 + wadd;
            #pragma unroll
            for (int r = 0; r < 16; r++) {
                const int m = rowM + r;
                const float eim = eis[m];
                float2 bv = *(const float2*)&bsm[m * 64 + 2 * lane];
                const uint32_t word = adjS[m * 16 + wbase];
                const bool m0 = (word >> bitpos) & 1u;
                const bool m1 = (word >> (bitpos + 1)) & 1u;
                float x0 = eim + ejv.x;
                float x1 = eim + ejv.y;
                x0 = (x0 > 0.f ? x0 : ALPHA * x0) + bv.x;
                x1 = (x1 > 0.f ? x1 : ALPHA * x1) + bv.y;
                float p0 = m0 ? __expf(x0) : 0.f;
                float p1 = m1 ? __expf(x1) : 0.f;
                sump[r] += p0 + p1;
                *(uint32_t*)(smem + SM_PH + m * 144 + lane * 4) = pack_h2(p0, p1);
            }
        }

        if (jt < 7) CP_WAIT(1);   // B(jt) complete; bias(jt+1) may pend
        else        CP_WAIT(0);
        __syncthreads();          // PH + BH visible

        // ---- HMMA phase ----
        #pragma unroll
        for (int ks = 0; ks < 4; ks++) {
            uint32_t ap[4];
            ldsm_x4(ap, aAddr + ks * 32);
            #pragma unroll
            for (int g = 0; g < 8; g++) {
                uint32_t bw[4];
                ldsm_x4(bw, bAddr + g * 16 * 144 + ks * 32);
                mma_f16(acc[g * 2],     ap, bw[0], bw[1]);
                mma_f16(acc[g * 2 + 1], ap, bw[2], bw[3]);
            }
        }
    }

    // ---- one-time row-sum reduction ----
    __syncthreads();
    float* red = (float*)(smem + SM_PH);   // [128][33] padded
    #pragma unroll
    for (int r = 0; r < 16; r++)
        red[(rowM + r) * 33 + lane] = sump[r];
    __syncthreads();
    if (t < 128) {
        float s = 0.f;
        #pragma unroll
        for (int k = 0; k < 32; k++) s += red[t * 33 + k];
        ssum[t] = s;
    }
    __syncthreads();

    // ---- epilogue: divide by row sum, ELU, store ----
    const int g  = lane >> 2;
    const int i2 = (lane & 3) * 2;
    const int r0 = wid * 16 + g;
    const int r1 = r0 + 8;
    const float inv0 = 1.f / ssum[r0];
    const float inv1 = 1.f / ssum[r1];
    float* o0 = out + ((size_t)b * L + i0 + r0) * FOUT;
    float* o1 = out + ((size_t)b * L + i0 + r1) * FOUT;
    #pragma unroll
    for (int nt = 0; nt < 16; nt++) {
        float v0 = acc[nt][0] * inv0, v1 = acc[nt][1] * inv0;
        float v2 = acc[nt][2] * inv1, v3 = acc[nt][3] * inv1;
        v0 = v0 > 0.f ? v0 : expm1f(v0);
        v1 = v1 > 0.f ? v1 : expm1f(v1);
        v2 = v2 > 0.f ? v2 : expm1f(v2);
        v3 = v3 > 0.f ? v3 : expm1f(v3);
        float2 w0 = {v0, v1}, w1 = {v2, v3};
        *(float2*)(o0 + nt * 8 + i2) = w0;
        *(float2*)(o1 + nt * 8 + i2) = w1;
    }
}

// ---------------------------------------------------------------------------
extern "C" void kernel_launch(void* const* d_in, const int* in_sizes, int n_in,
                              void* d_out, int out_size) {
    const float* h    = (const float*)d_in[0];
    const float* W    = (const float*)d_in[1];
    const float* a    = (const float*)d_in[2];
    const float* bias = (const float*)d_in[3];
    const void*  adj  = d_in[4];
    float* out = (float*)d_out;

    k_prep<<<64, 256>>>((const unsigned int*)adj, W);

    cudaFuncSetAttribute(k_gemm1, cudaFuncAttributeMaxDynamicSharedMemorySize, G1_TOTAL);
    k_gemm1<<<(B * L) / 128, 256, G1_TOTAL>>>(h, a);

    cudaFuncSetAttribute(k_attn, cudaFuncAttributeMaxDynamicSharedMemorySize, SM_TOTAL);
    dim3 grid(L / 128, B);
    k_attn<<<grid, 256, SM_TOTAL>>>(bias, out);
}

// round 13
// speedup vs baseline: 3.8210x; 1.0543x over previous
#include <cuda_runtime.h>
#include <cuda_bf16.h>
#include <cuda_fp16.h>
#include <math.h>
#include <stdint.h>

#define B    128
#define L    512
#define FIN  128
#define FOUT 128
#define ALPHA 0.2f

// Scratch (device globals — no allocation allowed)
__device__ __half g_WhT[(size_t)B * FOUT * L];          // Wh^T fp16: [b][n][l]
__device__ __nv_bfloat16 g_WTh[FOUT * FIN];             // W^T bf16 hi: [n][k]
__device__ __nv_bfloat16 g_WTl[FOUT * FIN];             // W^T bf16 lo
__device__ float g_ei[B * L];
__device__ float g_ej[B * L];
__device__ uint32_t g_adjBits[512 * 16];                // adj bitmask

// ============================ helpers ============================
__device__ __forceinline__ uint32_t smem_u32(const void* p) {
    uint32_t a;
    asm("{ .reg .u64 t; cvta.to.shared.u64 t, %1; cvt.u32.u64 %0, t; }"
        : "=r"(a) : "l"(p));
    return a;
}
__device__ __forceinline__ void ldsm_x4(uint32_t* r, uint32_t addr) {
    asm volatile("ldmatrix.sync.aligned.m8n8.x4.shared.b16 {%0,%1,%2,%3}, [%4];"
                 : "=r"(r[0]), "=r"(r[1]), "=r"(r[2]), "=r"(r[3]) : "r"(addr));
}
__device__ __forceinline__ void mma_bf16(float* c, const uint32_t* a,
                                         uint32_t b0, uint32_t b1) {
    asm volatile(
        "mma.sync.aligned.m16n8k16.row.col.f32.bf16.bf16.f32 "
        "{%0,%1,%2,%3}, {%4,%5,%6,%7}, {%8,%9}, {%0,%1,%2,%3};"
        : "+f"(c[0]), "+f"(c[1]), "+f"(c[2]), "+f"(c[3])
        : "r"(a[0]), "r"(a[1]), "r"(a[2]), "r"(a[3]), "r"(b0), "r"(b1));
}
__device__ __forceinline__ void mma_f16(float* c, const uint32_t* a,
                                        uint32_t b0, uint32_t b1) {
    asm volatile(
        "mma.sync.aligned.m16n8k16.row.col.f32.f16.f16.f32 "
        "{%0,%1,%2,%3}, {%4,%5,%6,%7}, {%8,%9}, {%0,%1,%2,%3};"
        : "+f"(c[0]), "+f"(c[1]), "+f"(c[2]), "+f"(c[3])
        : "r"(a[0]), "r"(a[1]), "r"(a[2]), "r"(a[3]), "r"(b0), "r"(b1));
}
__device__ __forceinline__ uint32_t pack_bf2(__nv_bfloat16 a, __nv_bfloat16 b) {
    return (uint32_t)__bfloat16_as_ushort(a) | ((uint32_t)__bfloat16_as_ushort(b) << 16);
}
__device__ __forceinline__ uint32_t pack_h2(float a, float b) {
    __half2 h = __floats2half2_rn(a, b);
    return *(uint32_t*)&h;
}
#define CP_ASYNC16(dst, src) \
    asm volatile("cp.async.cg.shared.global [%0], [%1], 16;" \
                 :: "r"(dst), "l"(src) : "memory")
#define CP_COMMIT() asm volatile("cp.async.commit_group;" ::: "memory")
#define CP_WAIT(n)  asm volatile("cp.async.wait_group %0;" :: "n"(n) : "memory")

// ---------------------------------------------------------------------------
// Kernel 0: mask-kind detect (block-local), W split/transpose, adj -> bitmask
// ---------------------------------------------------------------------------
__global__ void k_prep(const unsigned int* __restrict__ m,
                       const float* __restrict__ W) {
    __shared__ int sgt1, sflt;
    const int t = threadIdx.x;
    if (t == 0) { sgt1 = 0; sflt = 0; }
    __syncthreads();
    {
        unsigned w = m[t];
        if (w == 0x3F800000u) atomicOr(&sflt, 1);
        else if (w > 1u)      atomicOr(&sgt1, 1);
    }
    __syncthreads();
    const int kind = sflt ? 2 : (sgt1 ? 1 : 0);

    for (int idx = blockIdx.x * blockDim.x + t; idx < FIN * FOUT;
         idx += gridDim.x * blockDim.x) {
        int n = idx >> 7, k = idx & 127;
        float v = W[k * FOUT + n];
        __nv_bfloat16 hi = __float2bfloat16(v);
        __nv_bfloat16 lo = __float2bfloat16(v - __bfloat162float(hi));
        g_WTh[idx] = hi;
        g_WTl[idx] = lo;
    }

    const int wid = t >> 5, lane = t & 31;
    const int row = blockIdx.x * 8 + wid;
    const int* adjI = (const int*)m;
    const unsigned char* adjB = (const unsigned char*)m;
    const float* adjF = (const float*)m;
    #pragma unroll
    for (int w = 0; w < 16; w++) {
        const int e = row * 512 + w * 32 + lane;
        bool v;
        if (kind == 0)      v = adjI[e] != 0;
        else if (kind == 1) v = adjB[e] != 0;
        else                v = adjF[e] != 0.f;
        unsigned word = __ballot_sync(0xFFFFFFFFu, v);
        if (lane == 0) g_adjBits[row * 16 + w] = word;
    }
}

// ---------------------------------------------------------------------------
// Kernel 1: Wh = h @ W on HMMA (split bf16, 3 chains). Unchanged (validated).
// ---------------------------------------------------------------------------
#define G1_AH 0
#define G1_AL 18432
#define G1_WH 36864
#define G1_WL 55296
#define G1_AV 73728
#define G1_TOTAL 74752
#define TSTRIDE 272

__global__ __launch_bounds__(256, 2) void k_gemm1(const float* __restrict__ h,
                                                  const float* __restrict__ a) {
    extern __shared__ char sm[];
    const uint32_t sb = smem_u32(sm);

    const int t    = threadIdx.x;
    const int wid  = t >> 5;
    const int lane = t & 31;
    const long rowBase = (long)blockIdx.x * 128;
    const int  bIdx  = (int)(rowBase >> 9);
    const int  lBase = (int)(rowBase & 511);

    if (t < 64) *(float4*)(sm + G1_AV + t * 16) = *(const float4*)(a + t * 4);

    float acc[16][4];
    #pragma unroll
    for (int n = 0; n < 16; n++)
        #pragma unroll
        for (int c = 0; c < 4; c++) acc[n][c] = 0.f;

    const int aRow  = wid * 16 + (lane & 15);
    const int aKoff = (lane >> 4) * 16;
    const uint32_t aAddrH = sb + G1_AH + aRow * 144 + aKoff;
    const uint32_t aAddrL = sb + G1_AL + aRow * 144 + aKoff;
    const int bRow  = (lane & 7) + ((lane >> 4) << 3);
    const int bKoff = ((lane >> 3) & 1) * 16;
    const uint32_t bAddrH = sb + G1_WH + bRow * 144 + bKoff;
    const uint32_t bAddrL = sb + G1_WL + bRow * 144 + bKoff;

    for (int kc = 0; kc < FIN; kc += 64) {
        __syncthreads();
        #pragma unroll
        for (int i = 0; i < 8; i++) {
            const int idx = t + 256 * i;
            const int mm = idx >> 4, k4 = idx & 15;
            float4 v = *(const float4*)(h + (rowBase + mm) * FIN + kc + k4 * 4);
            __nv_bfloat16 h0 = __float2bfloat16(v.x), h1 = __float2bfloat16(v.y);
            __nv_bfloat16 h2 = __float2bfloat16(v.z), h3 = __float2bfloat16(v.w);
            uint2 hv = {pack_bf2(h0, h1), pack_bf2(h2, h3)};
            uint2 lv = {pack_bf2(__float2bfloat16(v.x - __bfloat162float(h0)),
                                 __float2bfloat16(v.y - __bfloat162float(h1))),
                        pack_bf2(__float2bfloat16(v.z - __bfloat162float(h2)),
                                 __float2bfloat16(v.w - __bfloat162float(h3)))};
            *(uint2*)(sm + G1_AH + mm * 144 + k4 * 8) = hv;
            *(uint2*)(sm + G1_AL + mm * 144 + k4 * 8) = lv;
        }
        #pragma unroll
        for (int i = 0; i < 4; i++) {
            const int idx = t + 256 * i;
            const int n = idx >> 3, c = idx & 7;
            *(uint4*)(sm + G1_WH + n * 144 + c * 16) =
                *(const uint4*)(g_WTh + n * FIN + kc + c * 8);
            *(uint4*)(sm + G1_WL + n * 144 + c * 16) =
                *(const uint4*)(g_WTl + n * FIN + kc + c * 8);
        }
        __syncthreads();

        #pragma unroll
        for (int ks = 0; ks < 4; ks++) {
            uint32_t ah[4], al[4];
            ldsm_x4(ah, aAddrH + ks * 32);
            ldsm_x4(al, aAddrL + ks * 32);
            #pragma unroll
            for (int g = 0; g < 8; g++) {
                uint32_t bh[4], bl[4];
                ldsm_x4(bh, bAddrH + g * 16 * 144 + ks * 32);
                ldsm_x4(bl, bAddrL + g * 16 * 144 + ks * 32);
                mma_bf16(acc[g * 2],     ah, bh[0], bh[1]);
                mma_bf16(acc[g * 2 + 1], ah, bh[2], bh[3]);
                mma_bf16(acc[g * 2],     ah, bl[0], bl[1]);
                mma_bf16(acc[g * 2 + 1], ah, bl[2], bl[3]);
                mma_bf16(acc[g * 2],     al, bh[0], bh[1]);
                mma_bf16(acc[g * 2 + 1], al, bh[2], bh[3]);
            }
        }
    }

    {
        const float* as1 = (const float*)(sm + G1_AV);
        const float* as2 = as1 + 128;
        const int k2 = (lane & 3) * 2;
        float e1a = 0.f, e2a = 0.f, e1b = 0.f, e2b = 0.f;
        #pragma unroll
        for (int nt = 0; nt < 16; nt++) {
            const int c0 = nt * 8 + k2;
            float2 a1v = *(const float2*)&as1[c0];
            float2 a2v = *(const float2*)&as2[c0];
            e1a += acc[nt][0] * a1v.x + acc[nt][1] * a1v.y;
            e2a += acc[nt][0] * a2v.x + acc[nt][1] * a2v.y;
            e1b += acc[nt][2] * a1v.x + acc[nt][3] * a1v.y;
            e2b += acc[nt][2] * a2v.x + acc[nt][3] * a2v.y;
        }
        #pragma unroll
        for (int o = 1; o <= 2; o <<= 1) {
            e1a += __shfl_xor_sync(0xFFFFFFFFu, e1a, o);
            e2a += __shfl_xor_sync(0xFFFFFFFFu, e2a, o);
            e1b += __shfl_xor_sync(0xFFFFFFFFu, e1b, o);
            e2b += __shfl_xor_sync(0xFFFFFFFFu, e2b, o);
        }
        if ((lane & 3) == 0) {
            const int r0 = wid * 16 + (lane >> 2);
            g_ei[rowBase + r0]     = e1a;
            g_ej[rowBase + r0]     = e2a;
            g_ei[rowBase + r0 + 8] = e1b;
            g_ej[rowBase + r0 + 8] = e2b;
        }
    }

    __syncthreads();
    char* TH = sm;
    {
        const int r0 = wid * 16 + (lane >> 2);
        const int k2 = (lane & 3) * 2;
        #pragma unroll
        for (int nt = 0; nt < 16; nt++) {
            const int c0 = nt * 8 + k2;
            #pragma unroll
            for (int q = 0; q < 4; q++) {
                const int cc = c0 + (q & 1);
                const int mm = r0 + (q >> 1) * 8;
                *(__half*)(TH + cc * TSTRIDE + mm * 2) = __float2half_rn(acc[nt][q]);
            }
        }
    }
    __syncthreads();
    #pragma unroll
    for (int i = 0; i < 8; i++) {
        const int idx = t + 256 * i;
        const int n = idx >> 4, c = idx & 15;
        const size_t go = ((size_t)bIdx * FOUT + n) * L + lBase + c * 8;
        *(uint4*)(g_WhT + go) = *(uint4*)(TH + n * TSTRIDE + c * 16);
    }
}

// ---------------------------------------------------------------------------
// Kernel 2: fused attention, fp16 HMMA. R13: p computed DIRECTLY in the MMA
// A-fragment register layout — no p smem, no A ldsm. Row sums accumulate in
// fragment layout; one butterfly shuffle at the end (no smem reduction).
// Pipeline skeleton identical to R12 (bias double-buffer + B-in-flight).
// bias smem stride = 68 floats (272B, 16B-aligned, <=2-way LDS conflict).
// ---------------------------------------------------------------------------
#define SM_BH   0        // 18432
#define SM_BIAS 18432    // 2 x 34816
#define SM_ADJ  88064    // 8192
#define SM_EJ   96256    // 2048
#define SM_EI   98304    // 512
#define SM_TOTAL 98816

__global__ __launch_bounds__(256, 2) void k_attn(const float* __restrict__ bias,
                                                 float* __restrict__ out) {
    extern __shared__ char smem[];
    const uint32_t sb = smem_u32(smem);

    const int t    = threadIdx.x;
    const int wid  = t >> 5;
    const int lane = t & 31;
    const int b    = blockIdx.y;
    const int i0   = blockIdx.x * 128;

    float* ejs  = (float*)(smem + SM_EJ);
    float* eis  = (float*)(smem + SM_EI);
    uint32_t* adjS = (uint32_t*)(smem + SM_ADJ);

    if (t < 128) {
        *(float4*)&ejs[t * 4] = *(const float4*)&g_ej[b * L + t * 4];
        eis[t] = g_ei[b * L + i0 + t];
    }
    #pragma unroll
    for (int i = 0; i < 8; i++) {
        const int idx = t + 256 * i;
        adjS[idx] = g_adjBits[(i0 + (idx >> 4)) * 16 + (idx & 15)];
    }

    const size_t biasCta = ((size_t)b * L + i0) * L;
    const size_t whtCta  = (size_t)b * FOUT * L;

    // prologue: bias(0) -> buf 0  [group]; stride 272B, 16B chunks
    {
        const uint32_t d0 = sb + SM_BIAS;
        #pragma unroll
        for (int i = 0; i < 8; i++) {
            const int idx = t + 256 * i;
            const int row = idx >> 4, c = idx & 15;
            CP_ASYNC16(d0 + row * 272 + c * 16,
                       bias + biasCta + (size_t)row * L + c * 4);
        }
        CP_COMMIT();
    }

    float acc[16][4];
    #pragma unroll
    for (int n = 0; n < 16; n++)
        #pragma unroll
        for (int c = 0; c < 4; c++) acc[n][c] = 0.f;

    const int g  = lane >> 2;        // fragment row group
    const int cc = lane & 3;         // fragment col group
    const int rowM = wid * 16;

    const int bRow  = (lane & 7) + ((lane >> 4) << 3);
    const int bKoff = ((lane >> 3) & 1) * 16;
    const uint32_t bAddr = sb + SM_BH + bRow * 144 + bKoff;

    __syncthreads();   // eis/ejs/adjS visible
    const float eil = eis[rowM + g];
    const float eih = eis[rowM + g + 8];

    float sumLo = 0.f, sumHi = 0.f;

    for (int jt = 0; jt < 8; jt++) {
        __syncthreads();   // MMA(jt-1) done reading BH; p(jt-1) done w/ bias buf

        // ---- B(jt) -> BH via cp.async (own group; completes during p-phase)
        {
            const size_t bbase = whtCta + (size_t)jt * 64;
            #pragma unroll
            for (int i = 0; i < 4; i++) {
                const int idx = t + 256 * i;
                const int n = idx >> 3, c = idx & 7;
                CP_ASYNC16(sb + SM_BH + n * 144 + c * 16,
                           g_WhT + bbase + (size_t)n * L + c * 8);
            }
            CP_COMMIT();
        }
        // ---- bias(jt+1) -> other buffer
        if (jt < 7) {
            const uint32_t d0 = sb + SM_BIAS + ((jt + 1) & 1) * 34816;
            const size_t srcB = biasCta + (size_t)(jt + 1) * 64;
            #pragma unroll
            for (int i = 0; i < 8; i++) {
                const int idx = t + 256 * i;
                const int row = idx >> 4, c = idx & 15;
                CP_ASYNC16(d0 + row * 272 + c * 16,
                           bias + srcB + (size_t)row * L + c * 4);
            }
            CP_COMMIT();
            CP_WAIT(2);    // bias(jt) complete
        } else {
            CP_WAIT(1);    // bias(7) complete
        }
        __syncthreads();

        // ---- p-phase: compute A fragments in registers ----
        uint32_t apAll[4][4];
        {
            const float* bsm = (const float*)(smem + SM_BIAS + (jt & 1) * 34816);
            const float* ejT = ejs + jt * 64;
            const uint32_t wl0 = adjS[(rowM + g) * 16 + jt * 2];
            const uint32_t wl1 = adjS[(rowM + g) * 16 + jt * 2 + 1];
            const uint32_t wh0 = adjS[(rowM + g + 8) * 16 + jt * 2];
            const uint32_t wh1 = adjS[(rowM + g + 8) * 16 + jt * 2 + 1];
            #pragma unroll
            for (int ks = 0; ks < 4; ks++) {
                const int c0 = ks * 16 + cc * 2;        // 0..63
                const uint32_t wl = (ks < 2) ? wl0 : wl1;
                const uint32_t wh = (ks < 2) ? wh0 : wh1;
                const int bb = (ks & 1) * 16 + cc * 2;  // bit base within word
                float2 ejA = *(const float2*)&ejT[c0];
                float2 ejB = *(const float2*)&ejT[c0 + 8];
                float2 bl0 = *(const float2*)&bsm[(rowM + g) * 68 + c0];
                float2 bl8 = *(const float2*)&bsm[(rowM + g) * 68 + c0 + 8];
                float2 bh0 = *(const float2*)&bsm[(rowM + g + 8) * 68 + c0];
                float2 bh8 = *(const float2*)&bsm[(rowM + g + 8) * 68 + c0 + 8];

                float x;
                x = eil + ejA.x; x = (x > 0.f ? x : ALPHA * x) + bl0.x;
                float pl0 = ((wl >> bb) & 1u)       ? __expf(x) : 0.f;
                x = eil + ejA.y; x = (x > 0.f ? x : ALPHA * x) + bl0.y;
                float pl1 = ((wl >> (bb + 1)) & 1u) ? __expf(x) : 0.f;
                x = eil + ejB.x; x = (x > 0.f ? x : ALPHA * x) + bl8.x;
                float pl8 = ((wl >> (bb + 8)) & 1u) ? __expf(x) : 0.f;
                x = eil + ejB.y; x = (x > 0.f ? x : ALPHA * x) + bl8.y;
                float pl9 = ((wl >> (bb + 9)) & 1u) ? __expf(x) : 0.f;
                x = eih + ejA.x; x = (x > 0.f ? x : ALPHA * x) + bh0.x;
                float ph0 = ((wh >> bb) & 1u)       ? __expf(x) : 0.f;
                x = eih + ejA.y; x = (x > 0.f ? x : ALPHA * x) + bh0.y;
                float ph1 = ((wh >> (bb + 1)) & 1u) ? __expf(x) : 0.f;
                x = eih + ejB.x; x = (x > 0.f ? x : ALPHA * x) + bh8.x;
                float ph8 = ((wh >> (bb + 8)) & 1u) ? __expf(x) : 0.f;
                x = eih + ejB.y; x = (x > 0.f ? x : ALPHA * x) + bh8.y;
                float ph9 = ((wh >> (bb + 9)) & 1u) ? __expf(x) : 0.f;

                sumLo += (pl0 + pl1) + (pl8 + pl9);
                sumHi += (ph0 + ph1) + (ph8 + ph9);
                apAll[ks][0] = pack_h2(pl0, pl1);
                apAll[ks][1] = pack_h2(ph0, ph1);
                apAll[ks][2] = pack_h2(pl8, pl9);
                apAll[ks][3] = pack_h2(ph8, ph9);
            }
        }

        if (jt < 7) CP_WAIT(1);   // B(jt) complete
        else        CP_WAIT(0);
        __syncthreads();          // BH visible to all threads

        // ---- HMMA phase (A from registers, B from smem) ----
        #pragma unroll
        for (int ks = 0; ks < 4; ks++) {
            #pragma unroll
            for (int g2 = 0; g2 < 8; g2++) {
                uint32_t bw[4];
                ldsm_x4(bw, bAddr + g2 * 16 * 144 + ks * 32);
                mma_f16(acc[g2 * 2],     apAll[ks], bw[0], bw[1]);
                mma_f16(acc[g2 * 2 + 1], apAll[ks], bw[2], bw[3]);
            }
        }
    }

    // ---- row sums: butterfly over the 4 col-group lanes ----
    #pragma unroll
    for (int o = 1; o <= 2; o <<= 1) {
        sumLo += __shfl_xor_sync(0xFFFFFFFFu, sumLo, o);
        sumHi += __shfl_xor_sync(0xFFFFFFFFu, sumHi, o);
    }
    const float inv0 = 1.f / sumLo;
    const float inv1 = 1.f / sumHi;

    // ---- epilogue: divide by row sum, ELU, store ----
    const int i2 = cc * 2;
    const int r0 = rowM + g;
    const int r1 = r0 + 8;
    float* o0 = out + ((size_t)b * L + i0 + r0) * FOUT;
    float* o1 = out + ((size_t)b * L + i0 + r1) * FOUT;
    #pragma unroll
    for (int nt = 0; nt < 16; nt++) {
        float v0 = acc[nt][0] * inv0, v1 = acc[nt][1] * inv0;
        float v2 = acc[nt][2] * inv1, v3 = acc[nt][3] * inv1;
        v0 = v0 > 0.f ? v0 : expm1f(v0);
        v1 = v1 > 0.f ? v1 : expm1f(v1);
        v2 = v2 > 0.f ? v2 : expm1f(v2);
        v3 = v3 > 0.f ? v3 : expm1f(v3);
        float2 w0 = {v0, v1}, w1 = {v2, v3};
        *(float2*)(o0 + nt * 8 + i2) = w0;
        *(float2*)(o1 + nt * 8 + i2) = w1;
    }
}

// ---------------------------------------------------------------------------
extern "C" void kernel_launch(void* const* d_in, const int* in_sizes, int n_in,
                              void* d_out, int out_size) {
    const float* h    = (const float*)d_in[0];
    const float* W    = (const float*)d_in[1];
    const float* a    = (const float*)d_in[2];
    const float* bias = (const float*)d_in[3];
    const void*  adj  = d_in[4];
    float* out = (float*)d_out;

    k_prep<<<64, 256>>>((const unsigned int*)adj, W);

    cudaFuncSetAttribute(k_gemm1, cudaFuncAttributeMaxDynamicSharedMemorySize, G1_TOTAL);
    k_gemm1<<<(B * L) / 128, 256, G1_TOTAL>>>(h, a);

    cudaFuncSetAttribute(k_attn, cudaFuncAttributeMaxDynamicSharedMemorySize, SM_TOTAL);
    dim3 grid(L / 128, B);
    k_attn<<<grid, 256, SM_TOTAL>>>(bias, out);
}